// round 7
// baseline (speedup 1.0000x reference)
#include <cuda_runtime.h>
#include <cuda_bf16.h>
#include <cstdint>
#include <math.h>

#define BATCH 4
#define TSEQ  2048
#define CDIM  1024
#define NH    16
#define HD    64
#define BT    (BATCH * TSEQ)
#define K3    (3 * CDIM)          // split-extended K dimension = 3072
#define NKT   (TSEQ / 64)         // 32 key tiles per (b,h)

// ---------------------------------------------------------------------------
// Scratch (__device__ globals; no allocation allowed)
// ---------------------------------------------------------------------------
__device__ float g_qkv[(size_t)BT * 3 * CDIM];             // [B*T, 3C] fp32
__device__ __nv_bfloat16 g_xs[(size_t)BT * K3];            // x split  [hi|hi|lo]
__device__ __nv_bfloat16 g_as[(size_t)BT * K3];            // att split[hi|hi|lo]
__device__ __nv_bfloat16 g_wqs[(size_t)3 * CDIM * K3];     // W_qkv    [hi|lo|hi]
__device__ __nv_bfloat16 g_wps[(size_t)CDIM * K3];         // W_proj   [hi|lo|hi]
// Pre-split K/V: per (b,h,kt) 16KB block = [hi 8KB | lo 8KB], smem-layout bytes
__device__ char g_ksp[(size_t)BATCH * NH * NKT * 16384];
__device__ char g_vsp[(size_t)BATCH * NH * NKT * 16384];

// ---------------------------------------------------------------------------
// PTX helpers (sm_100-baseline safe: cp.async + ldmatrix + mma.sync only)
// ---------------------------------------------------------------------------
__device__ __forceinline__ uint32_t smem_u32(const void* p) {
    uint32_t a;
    asm("{ .reg .u64 t; cvta.to.shared.u64 t, %1; cvt.u32.u64 %0, t; }"
        : "=r"(a) : "l"(p));
    return a;
}

#define CPASYNC16(dst, src) \
    asm volatile("cp.async.cg.shared.global [%0], [%1], 16;" \
        :: "r"(dst), "l"(src))
#define CPASYNC_COMMIT() asm volatile("cp.async.commit_group;")
#define CPASYNC_WAIT1()  asm volatile("cp.async.wait_group 1;")
#define CPASYNC_WAIT2()  asm volatile("cp.async.wait_group 2;")

#define LDSM_X4(r, addr) \
    asm volatile("ldmatrix.sync.aligned.m8n8.x4.shared.b16 {%0,%1,%2,%3}, [%4];" \
        : "=r"((r)[0]), "=r"((r)[1]), "=r"((r)[2]), "=r"((r)[3]) : "r"(addr))

#define LDSM_X4_T(r, addr) \
    asm volatile("ldmatrix.sync.aligned.m8n8.x4.trans.shared.b16 {%0,%1,%2,%3}, [%4];" \
        : "=r"((r)[0]), "=r"((r)[1]), "=r"((r)[2]), "=r"((r)[3]) : "r"(addr))

#define MMA_BF16(d, a, br0, br1) \
    asm volatile("mma.sync.aligned.m16n8k16.row.col.f32.bf16.bf16.f32 " \
        "{%0,%1,%2,%3}, {%4,%5,%6,%7}, {%8,%9}, {%0,%1,%2,%3};" \
        : "+f"((d)[0]), "+f"((d)[1]), "+f"((d)[2]), "+f"((d)[3]) \
        : "r"((a)[0]), "r"((a)[1]), "r"((a)[2]), "r"((a)[3]), "r"(br0), "r"(br1))

// pack two f32 -> bf16x2 (lo = x0, hi = x1)
#define PACK_BF16X2(res, x0, x1) \
    asm("cvt.rn.bf16x2.f32 %0, %1, %2;" : "=r"(res) : "f"(x1), "f"(x0))

// ---------------------------------------------------------------------------
// Split fp32 [R, 1024] -> bf16 [R, 3072]:
// A operand: hi @0, hi @1024, lo @2048   -> A' = [hi|hi|lo]
// B operand: hi @0, lo @1024, hi @2048   -> B' = [hi|lo|hi]
// A'.B'^T = hi.hi + hi.lo + lo.hi  (lo.lo term ~2^-18, dropped)
// ---------------------------------------------------------------------------
__global__ __launch_bounds__(256) void split_kernel(
    const float* __restrict__ src, __nv_bfloat16* __restrict__ dst,
    int hi2_off, int lo_off)
{
    int idx = blockIdx.x * blockDim.x + threadIdx.x;
    int row = idx >> 7;            // K/8 = 128 chunks per row
    int c8  = (idx & 127) << 3;

    const float* p = src + (size_t)row * CDIM + c8;
    float4 v0 = *(const float4*)p;
    float4 v1 = *(const float4*)(p + 4);
    float xs[8] = {v0.x, v0.y, v0.z, v0.w, v1.x, v1.y, v1.z, v1.w};

    uint32_t hv[4], lv[4];
    #pragma unroll
    for (int i = 0; i < 4; i++) {
        float x0 = xs[2*i], x1 = xs[2*i + 1];
        uint32_t ph; PACK_BF16X2(ph, x0, x1);
        float h0 = __uint_as_float(ph << 16);
        float h1 = __uint_as_float(ph & 0xffff0000u);
        uint32_t pl; PACK_BF16X2(pl, x0 - h0, x1 - h1);
        hv[i] = ph; lv[i] = pl;
    }
    uint4 hq = make_uint4(hv[0], hv[1], hv[2], hv[3]);
    uint4 lq = make_uint4(lv[0], lv[1], lv[2], lv[3]);

    __nv_bfloat16* base = dst + (size_t)row * K3;
    *reinterpret_cast<uint4*>(base + c8)           = hq;
    *reinterpret_cast<uint4*>(base + hi2_off + c8) = hq;
    *reinterpret_cast<uint4*>(base + lo_off  + c8) = lq;
}

// ---------------------------------------------------------------------------
// Pre-split K/V tiles into smem-image blocks for verbatim cp.async.
// ---------------------------------------------------------------------------
__global__ __launch_bounds__(256) void presplit_kv_kernel(
    const float* __restrict__ qkv, char* __restrict__ ksp, char* __restrict__ vsp)
{
    const int tid = threadIdx.x;
    const int kt = blockIdx.x, h = blockIdx.y, b = blockIdx.z;
    size_t blk = ((size_t)((b * NH + h) * NKT + kt)) * 16384;
    char* kh = ksp + blk; char* kl = kh + 8192;
    char* vh = vsp + blk; char* vl = vh + 8192;
    const float* base = qkv + (size_t)(b * TSEQ + kt * 64) * 3072 + h * 64;

    for (int u = tid; u < 1024; u += 256) {
        int isV = u >> 9;
        int uu  = u & 511;
        int row = uu >> 3;
        int c8  = (uu & 7) * 8;
        const float* p = base + (size_t)row * 3072 + (isV ? 2048 : 1024) + c8;
        float4 v0 = *(const float4*)p;
        float4 v1 = *(const float4*)(p + 4);
        float xs[8] = {v0.x, v0.y, v0.z, v0.w, v1.x, v1.y, v1.z, v1.w};
        uint32_t hv[4], lv[4];
        #pragma unroll
        for (int i = 0; i < 4; i++) {
            float x0 = xs[2*i], x1 = xs[2*i + 1];
            uint32_t ph; PACK_BF16X2(ph, x0, x1);
            float h0 = __uint_as_float(ph << 16);
            float h1 = __uint_as_float(ph & 0xffff0000u);
            uint32_t pl; PACK_BF16X2(pl, x0 - h0, x1 - h1);
            hv[i] = ph; lv[i] = pl;
        }
        uint32_t off = row * 128 + ((uint32_t)(c8 * 2) ^ ((row & 7) << 4));
        char* dh = isV ? vh : kh;
        char* dl = isV ? vl : kl;
        *(uint4*)(dh + off) = make_uint4(hv[0], hv[1], hv[2], hv[3]);
        *(uint4*)(dl + off) = make_uint4(lv[0], lv[1], lv[2], lv[3]);
    }
}

// ---------------------------------------------------------------------------
// bf16 NT GEMM v2: CTA tile 128(M) x 256(N), BK=64, 3-stage cp.async ring.
// 8 warps as 2m x 4n; warp tile 64x64 (4 m-frags x 8 n-frags), acc 128 regs.
// ---------------------------------------------------------------------------
#define G2STG 49152            // A 16KB + B 32KB per stage
#define GEMM_SMEM (3 * G2STG)  // 147456

__global__ __launch_bounds__(256, 1) void gemm_bf16_kernel(
    const __nv_bfloat16* __restrict__ A, const __nv_bfloat16* __restrict__ B,
    const float* __restrict__ bias, float* __restrict__ C,
    int M, int N, int K)
{
    extern __shared__ char sm[];
    uint32_t smb = smem_u32(sm);
    const int tid  = threadIdx.x;
    const int lane = tid & 31;
    const int wid  = tid >> 5;
    const int wm   = wid >> 2;        // 0..1
    const int wn   = wid & 3;         // 0..3
    const int m0   = blockIdx.y * 128;
    const int n0   = blockIdx.x * 256;
    const int NK   = K >> 6;

    const size_t Kb = (size_t)K * 2;
    const char* Abase = (const char*)A + (size_t)m0 * Kb;
    const char* Bbase = (const char*)B + (size_t)n0 * Kb;

    float acc[4][8][4];
    #pragma unroll
    for (int i = 0; i < 4; i++)
        #pragma unroll
        for (int j = 0; j < 8; j++)
            #pragma unroll
            for (int r = 0; r < 4; r++) acc[i][j][r] = 0.f;

    const int lrow  = lane & 15;
    const int lhalf = (lane >> 4) << 4;
    const uint32_t rxor = (uint32_t)((lrow & 7) << 4);
    uint32_t arow[4], brow[4];
    #pragma unroll
    for (int mi = 0; mi < 4; mi++)
        arow[mi] = (uint32_t)((wm * 64 + mi * 16 + lrow) * 128);
    #pragma unroll
    for (int bi = 0; bi < 4; bi++)
        brow[bi] = (uint32_t)((wn * 64 + bi * 16 + lrow) * 128);

    auto load_stage = [&](int kt, int s) {
        uint32_t sa = smb + s * G2STG;
        uint32_t sb = sa + 16384;
        size_t ktb = (size_t)kt << 7;   // kt*128 bytes
        #pragma unroll
        for (int i = 0; i < 4; i++) {   // A: 128 rows x 8 x 16B
            int idx = tid + i * 256;
            int row = idx >> 3;
            uint32_t c16 = (uint32_t)((idx & 7) << 4);
            uint32_t so = row * 128 + (c16 ^ ((row & 7) << 4));
            CPASYNC16(sa + so, Abase + (size_t)row * Kb + ktb + c16);
        }
        #pragma unroll
        for (int i = 0; i < 8; i++) {   // B: 256 rows x 8 x 16B
            int idx = tid + i * 256;
            int row = idx >> 3;
            uint32_t c16 = (uint32_t)((idx & 7) << 4);
            uint32_t so = row * 128 + (c16 ^ ((row & 7) << 4));
            CPASYNC16(sb + so, Bbase + (size_t)row * Kb + ktb + c16);
        }
    };

    load_stage(0, 0); CPASYNC_COMMIT();
    load_stage(1, 1); CPASYNC_COMMIT();
    load_stage(2, 2); CPASYNC_COMMIT();

    int slot = 0;
    for (int kt = 0; kt < NK; kt++) {
        CPASYNC_WAIT2();
        __syncthreads();
        uint32_t sa = smb + slot * G2STG;
        uint32_t sb = sa + 16384;

        #pragma unroll
        for (int ks = 0; ks < 4; ks++) {
            uint32_t kb = (uint32_t)((ks << 5) + lhalf);
            uint32_t a[4][4], bf[4][4];
            #pragma unroll
            for (int mi = 0; mi < 4; mi++)
                LDSM_X4(a[mi], sa + arow[mi] + (kb ^ rxor));
            #pragma unroll
            for (int bi = 0; bi < 4; bi++)
                LDSM_X4(bf[bi], sb + brow[bi] + (kb ^ rxor));
            #pragma unroll
            for (int mi = 0; mi < 4; mi++)
                #pragma unroll
                for (int ni = 0; ni < 8; ni++)
                    MMA_BF16(acc[mi][ni], a[mi],
                             bf[ni >> 1][ni & 1], bf[ni >> 1][(ni & 1) + 2]);
        }
        __syncthreads();
        if (kt + 3 < NK) load_stage(kt + 3, slot);
        CPASYNC_COMMIT();
        slot = (slot == 2) ? 0 : slot + 1;
    }

    const int g  = lane >> 2;
    const int tg = (lane & 3) << 1;
    #pragma unroll
    for (int mi = 0; mi < 4; mi++) {
        int r0 = m0 + wm * 64 + mi * 16 + g;
        #pragma unroll
        for (int ni = 0; ni < 8; ni++) {
            int col = n0 + wn * 64 + ni * 8 + tg;
            float b0 = bias[col], b1 = bias[col + 1];
            float2 v0 = {acc[mi][ni][0] + b0, acc[mi][ni][1] + b1};
            float2 v1 = {acc[mi][ni][2] + b0, acc[mi][ni][3] + b1};
            *(float2*)&C[(size_t)r0 * N + col] = v0;
            *(float2*)&C[(size_t)(r0 + 8) * N + col] = v1;
        }
    }
}

// ---------------------------------------------------------------------------
// Flash attention via HMMA, bf16 hi/lo split, causal.
// K/V pre-split in GMEM -> double-buffered cp.async; epilogue writes the
// attention output DIRECTLY in split [hi|hi|lo] layout (g_as) for the proj GEMM.
// ---------------------------------------------------------------------------
#define FSTG 32768
#define FLASH_SMEM (32768 + 2 * FSTG)   // 98304

__global__ __launch_bounds__(256, 1) void flash_hmma_kernel(
    const float* __restrict__ qkv,
    const char* __restrict__ ksp, const char* __restrict__ vsp,
    __nv_bfloat16* __restrict__ outs)
{
    extern __shared__ char sm[];
    uint32_t smb = smem_u32(sm);
    const uint32_t sQh = smb;
    const uint32_t sQl = smb + 16384;
    char* Qh = sm;
    char* Ql = sm + 16384;

    const int tid  = threadIdx.x;
    const int lane = tid & 31;
    const int w    = tid >> 5;
    const int g    = lane >> 2;
    const int t    = lane & 3;
    const int qt   = (gridDim.x - 1) - blockIdx.x;   // heavy tiles first
    const int h    = blockIdx.y;
    const int b    = blockIdx.z;
    const int q0   = qt * 128;

    const float* qbase = qkv + (size_t)(b * TSEQ) * 3072 + h * 64;
    const char* kbh = ksp + ((size_t)((b * NH + h) * NKT)) * 16384;
    const char* vbh = vsp + ((size_t)((b * NH + h) * NKT)) * 16384;

    const int nkt = 2 * qt + 2;

    auto load_stage = [&](int kt2, int s) {
        uint32_t d = smb + 32768 + s * FSTG;
        const char* sk = kbh + (size_t)kt2 * 16384;
        const char* sv = vbh + (size_t)kt2 * 16384;
        #pragma unroll
        for (int i = 0; i < 4; i++) {
            uint32_t o = (uint32_t)(tid + i * 256) * 16;
            CPASYNC16(d + o, sk + o);
            CPASYNC16(d + 16384 + o, sv + o);
        }
    };

    load_stage(0, 0); CPASYNC_COMMIT();
    if (nkt > 1) load_stage(1, 1);
    CPASYNC_COMMIT();

    // ---- Load Q tile (128 x 64 fp32), scale by 0.125, split hi/lo to smem ----
    for (int u = tid; u < 1024; u += 256) {
        int row = u >> 3;
        int c8  = (u & 7) * 8;
        const float* p = qbase + (size_t)(q0 + row) * 3072 + c8;
        float4 v0 = *(const float4*)p;
        float4 v1 = *(const float4*)(p + 4);
        float xs[8] = {v0.x, v0.y, v0.z, v0.w, v1.x, v1.y, v1.z, v1.w};
        uint32_t hv[4], lv[4];
        #pragma unroll
        for (int i = 0; i < 4; i++) {
            float x0 = xs[2*i] * 0.125f, x1 = xs[2*i + 1] * 0.125f;
            uint32_t ph; PACK_BF16X2(ph, x0, x1);
            float h0 = __uint_as_float(ph << 16);
            float h1 = __uint_as_float(ph & 0xffff0000u);
            uint32_t pl; PACK_BF16X2(pl, x0 - h0, x1 - h1);
            hv[i] = ph; lv[i] = pl;
        }
        uint32_t off = row * 128 + ((uint32_t)(c8 * 2) ^ ((row & 7) << 4));
        *(uint4*)(Qh + off) = make_uint4(hv[0], hv[1], hv[2], hv[3]);
        *(uint4*)(Ql + off) = make_uint4(lv[0], lv[1], lv[2], lv[3]);
    }

    const int lrow  = lane & 15;
    const int lhalf = (lane >> 4) << 4;
    const uint32_t aoff = (uint32_t)((w * 16 + lrow) * 128);
    const uint32_t axor = (uint32_t)((lrow & 7) << 4);
    const uint32_t kxor = axor;

    float o[8][4];
    #pragma unroll
    for (int i = 0; i < 8; i++)
        #pragma unroll
        for (int j = 0; j < 4; j++) o[i][j] = 0.f;
    float m0 = -1e30f, m1 = -1e30f, l0 = 0.f, l1 = 0.f;
    const int qw = q0 + w * 16;

    for (int kt = 0; kt < nkt; kt++) {
        const int k0 = kt * 64;
        CPASYNC_WAIT1();
        __syncthreads();
        const uint32_t sKh = smb + 32768 + (kt & 1) * FSTG;
        const uint32_t sKl = sKh + 8192;
        const uint32_t sVh = sKh + 16384;
        const uint32_t sVl = sKh + 24576;

        float s[8][4];
        #pragma unroll
        for (int i = 0; i < 8; i++)
            #pragma unroll
            for (int j = 0; j < 4; j++) s[i][j] = 0.f;

        #pragma unroll
        for (int kc = 0; kc < 4; kc++) {
            uint32_t colb = (uint32_t)(kc * 32 + lhalf);
            uint32_t ah[4], al[4];
            LDSM_X4(ah, sQh + aoff + (colb ^ axor));
            LDSM_X4(al, sQl + aoff + (colb ^ axor));
            #pragma unroll
            for (int gk = 0; gk < 4; gk++) {
                uint32_t ro = (uint32_t)((gk * 16 + lrow) * 128);
                uint32_t kh[4], kl[4];
                LDSM_X4(kh, sKh + ro + (colb ^ kxor));
                LDSM_X4(kl, sKl + ro + (colb ^ kxor));
                #pragma unroll
                for (int pp = 0; pp < 2; pp++) {
                    int nt = gk * 2 + pp;
                    MMA_BF16(s[nt], ah, kh[pp], kh[pp + 2]);
                    MMA_BF16(s[nt], ah, kl[pp], kl[pp + 2]);
                    MMA_BF16(s[nt], al, kh[pp], kh[pp + 2]);
                }
            }
        }

        if (k0 + 63 > qw) {
            int r0 = qw + g, r1 = qw + g + 8;
            #pragma unroll
            for (int nt = 0; nt < 8; nt++) {
                int col = k0 + nt * 8 + 2 * t;
                if (col     > r0) s[nt][0] = -1e30f;
                if (col + 1 > r0) s[nt][1] = -1e30f;
                if (col     > r1) s[nt][2] = -1e30f;
                if (col + 1 > r1) s[nt][3] = -1e30f;
            }
        }

        float mx0 = -1e30f, mx1 = -1e30f;
        #pragma unroll
        for (int nt = 0; nt < 8; nt++) {
            mx0 = fmaxf(mx0, fmaxf(s[nt][0], s[nt][1]));
            mx1 = fmaxf(mx1, fmaxf(s[nt][2], s[nt][3]));
        }
        mx0 = fmaxf(mx0, __shfl_xor_sync(0xffffffffu, mx0, 1));
        mx0 = fmaxf(mx0, __shfl_xor_sync(0xffffffffu, mx0, 2));
        mx1 = fmaxf(mx1, __shfl_xor_sync(0xffffffffu, mx1, 1));
        mx1 = fmaxf(mx1, __shfl_xor_sync(0xffffffffu, mx1, 2));
        float mn0 = fmaxf(m0, mx0), mn1 = fmaxf(m1, mx1);
        float c0 = __expf(m0 - mn0), c1 = __expf(m1 - mn1);
        float sum0 = 0.f, sum1 = 0.f;
        #pragma unroll
        for (int nt = 0; nt < 8; nt++) {
            s[nt][0] = __expf(s[nt][0] - mn0);
            s[nt][1] = __expf(s[nt][1] - mn0);
            s[nt][2] = __expf(s[nt][2] - mn1);
            s[nt][3] = __expf(s[nt][3] - mn1);
            sum0 += s[nt][0] + s[nt][1];
            sum1 += s[nt][2] + s[nt][3];
        }
        sum0 += __shfl_xor_sync(0xffffffffu, sum0, 1);
        sum0 += __shfl_xor_sync(0xffffffffu, sum0, 2);
        sum1 += __shfl_xor_sync(0xffffffffu, sum1, 1);
        sum1 += __shfl_xor_sync(0xffffffffu, sum1, 2);
        l0 = l0 * c0 + sum0; l1 = l1 * c1 + sum1;
        m0 = mn0; m1 = mn1;
        #pragma unroll
        for (int nt = 0; nt < 8; nt++) {
            o[nt][0] *= c0; o[nt][1] *= c0;
            o[nt][2] *= c1; o[nt][3] *= c1;
        }

        uint32_t ph[16], pl[16];
        #pragma unroll
        for (int c2 = 0; c2 < 8; c2++) {
            int ib = (c2 >> 1) * 4 + (c2 & 1) * 2;
            uint32_t p01, p23;
            PACK_BF16X2(p01, s[c2][0], s[c2][1]);
            PACK_BF16X2(p23, s[c2][2], s[c2][3]);
            float h0 = __uint_as_float(p01 << 16);
            float h1 = __uint_as_float(p01 & 0xffff0000u);
            float h2 = __uint_as_float(p23 << 16);
            float h3 = __uint_as_float(p23 & 0xffff0000u);
            uint32_t q01, q23;
            PACK_BF16X2(q01, s[c2][0] - h0, s[c2][1] - h1);
            PACK_BF16X2(q23, s[c2][2] - h2, s[c2][3] - h3);
            ph[ib] = p01; ph[ib + 1] = p23;
            pl[ib] = q01; pl[ib + 1] = q23;
        }

        #pragma unroll
        for (int kc = 0; kc < 4; kc++) {
            const uint32_t* aH = &ph[kc * 4];
            const uint32_t* aL = &pl[kc * 4];
            uint32_t ro = (uint32_t)((kc * 16 + lrow) * 128);
            #pragma unroll
            for (int j = 0; j < 4; j++) {
                uint32_t cb = ((uint32_t)(j * 32 + lhalf)) ^ kxor;
                uint32_t vh[4], vl[4];
                LDSM_X4_T(vh, sVh + ro + cb);
                LDSM_X4_T(vl, sVl + ro + cb);
                MMA_BF16(o[2*j],     aH, vh[0], vh[1]);
                MMA_BF16(o[2*j + 1], aH, vh[2], vh[3]);
                MMA_BF16(o[2*j],     aH, vl[0], vl[1]);
                MMA_BF16(o[2*j + 1], aH, vl[2], vl[3]);
                MMA_BF16(o[2*j],     aL, vh[0], vh[1]);
                MMA_BF16(o[2*j + 1], aL, vh[2], vh[3]);
            }
        }

        __syncthreads();
        if (kt + 2 < nkt) load_stage(kt + 2, kt & 1);
        CPASYNC_COMMIT();
    }

    // ---- finalize: O /= l, write split bf16 [hi|hi|lo] rows of g_as ----
    float inv0 = 1.0f / l0, inv1 = 1.0f / l1;
    int r0 = qw + g, r1 = qw + g + 8;
    __nv_bfloat16* ab = outs + (size_t)(b * TSEQ) * K3 + h * 64;
    uint32_t* p0 = (uint32_t*)(ab + (size_t)r0 * K3);
    uint32_t* p1 = (uint32_t*)(ab + (size_t)r1 * K3);
    #pragma unroll
    for (int nt = 0; nt < 8; nt++) {
        int c2 = (nt * 8 + 2 * t) >> 1;      // uint32 index within row
        float y00 = o[nt][0] * inv0, y01 = o[nt][1] * inv0;
        float y10 = o[nt][2] * inv1, y11 = o[nt][3] * inv1;
        uint32_t h0p, h1p;
        PACK_BF16X2(h0p, y00, y01);
        PACK_BF16X2(h1p, y10, y11);
        float a0 = __uint_as_float(h0p << 16);
        float a1 = __uint_as_float(h0p & 0xffff0000u);
        float b0 = __uint_as_float(h1p << 16);
        float b1 = __uint_as_float(h1p & 0xffff0000u);
        uint32_t l0p, l1p;
        PACK_BF16X2(l0p, y00 - a0, y01 - a1);
        PACK_BF16X2(l1p, y10 - b0, y11 - b1);
        p0[c2] = h0p; p0[c2 + 512] = h0p; p0[c2 + 1024] = l0p;
        p1[c2] = h1p; p1[c2 + 512] = h1p; p1[c2 + 1024] = l1p;
    }
}

// ---------------------------------------------------------------------------
// Launch
// ---------------------------------------------------------------------------
extern "C" void kernel_launch(void* const* d_in, const int* in_sizes, int n_in,
                              void* d_out, int out_size)
{
    const float* x      = (const float*)d_in[0];
    const float* W_qkv  = (const float*)d_in[1];
    const float* b_qkv  = (const float*)d_in[2];
    const float* W_proj = (const float*)d_in[3];
    const float* b_proj = (const float*)d_in[4];
    float* out = (float*)d_out;

    float *qkv;
    __nv_bfloat16 *xs, *as, *wqs, *wps;
    char *ksp, *vsp;
    cudaGetSymbolAddress((void**)&qkv, g_qkv);
    cudaGetSymbolAddress((void**)&xs,  g_xs);
    cudaGetSymbolAddress((void**)&as,  g_as);
    cudaGetSymbolAddress((void**)&wqs, g_wqs);
    cudaGetSymbolAddress((void**)&wps, g_wps);
    cudaGetSymbolAddress((void**)&ksp, g_ksp);
    cudaGetSymbolAddress((void**)&vsp, g_vsp);

    cudaFuncSetAttribute(gemm_bf16_kernel,
                         cudaFuncAttributeMaxDynamicSharedMemorySize, GEMM_SMEM);
    cudaFuncSetAttribute(flash_hmma_kernel,
                         cudaFuncAttributeMaxDynamicSharedMemorySize, FLASH_SMEM);

    // Splits: A operands [hi|hi|lo], B operands [hi|lo|hi]
    split_kernel<<<BT * CDIM / 8 / 256, 256>>>(x, xs, CDIM, 2 * CDIM);
    split_kernel<<<3 * CDIM * CDIM / 8 / 256, 256>>>(W_qkv, wqs, 2 * CDIM, CDIM);
    split_kernel<<<CDIM * CDIM / 8 / 256, 256>>>(W_proj, wps, 2 * CDIM, CDIM);

    // 1) QKV projection (tensor cores, split-K', 128x256 tiles)
    gemm_bf16_kernel<<<dim3(3 * CDIM / 256, BT / 128), 256, GEMM_SMEM>>>(
        xs, wqs, b_qkv, qkv, BT, 3 * CDIM, K3);

    // 1b) Pre-split K/V into smem-image blocks
    presplit_kv_kernel<<<dim3(NKT, NH, BATCH), 256>>>(qkv, ksp, vsp);

    // 2) Causal flash attention (HMMA, split); writes att directly in split form
    flash_hmma_kernel<<<dim3(TSEQ / 128, NH, BATCH), 256, FLASH_SMEM>>>(
        qkv, ksp, vsp, as);

    // 3) Output projection (128x256 tiles)
    gemm_bf16_kernel<<<dim3(CDIM / 256, BT / 128), 256, GEMM_SMEM>>>(
        as, wps, b_proj, out, BT, CDIM, K3);
}

// round 8
// speedup vs baseline: 1.0571x; 1.0571x over previous
#include <cuda_runtime.h>
#include <cuda_bf16.h>
#include <cstdint>
#include <math.h>

#define BATCH 4
#define TSEQ  2048
#define CDIM  1024
#define NH    16
#define HD    64
#define BT    (BATCH * TSEQ)
#define K3    (3 * CDIM)          // split-extended K dimension = 3072
#define NKT   (TSEQ / 64)         // 32 key tiles per (b,h)

// ---------------------------------------------------------------------------
// Scratch (__device__ globals; no allocation allowed)
// ---------------------------------------------------------------------------
__device__ float g_qkv[(size_t)BT * 3 * CDIM];             // [B*T, 3C] fp32
__device__ __nv_bfloat16 g_xs[(size_t)BT * K3];            // x split  [hi|hi|lo]
__device__ __nv_bfloat16 g_as[(size_t)BT * K3];            // att split[hi|hi|lo]
__device__ __nv_bfloat16 g_wqs[(size_t)3 * CDIM * K3];     // W_qkv    [hi|lo|hi]
__device__ __nv_bfloat16 g_wps[(size_t)CDIM * K3];         // W_proj   [hi|lo|hi]
// Pre-split K/V: per (b,h,kt) 16KB block = [hi 8KB | lo 8KB], smem-layout bytes
__device__ char g_ksp[(size_t)BATCH * NH * NKT * 16384];
__device__ char g_vsp[(size_t)BATCH * NH * NKT * 16384];

// ---------------------------------------------------------------------------
// PTX helpers (sm_100-baseline safe: cp.async + ldmatrix + mma.sync only)
// ---------------------------------------------------------------------------
__device__ __forceinline__ uint32_t smem_u32(const void* p) {
    uint32_t a;
    asm("{ .reg .u64 t; cvta.to.shared.u64 t, %1; cvt.u32.u64 %0, t; }"
        : "=r"(a) : "l"(p));
    return a;
}

#define CPASYNC16(dst, src) \
    asm volatile("cp.async.cg.shared.global [%0], [%1], 16;" \
        :: "r"(dst), "l"(src))
#define CPASYNC_COMMIT() asm volatile("cp.async.commit_group;")
#define CPASYNC_WAIT1()  asm volatile("cp.async.wait_group 1;")
#define CPASYNC_WAIT2()  asm volatile("cp.async.wait_group 2;")

#define LDSM_X4(r, addr) \
    asm volatile("ldmatrix.sync.aligned.m8n8.x4.shared.b16 {%0,%1,%2,%3}, [%4];" \
        : "=r"((r)[0]), "=r"((r)[1]), "=r"((r)[2]), "=r"((r)[3]) : "r"(addr))

#define LDSM_X4_T(r, addr) \
    asm volatile("ldmatrix.sync.aligned.m8n8.x4.trans.shared.b16 {%0,%1,%2,%3}, [%4];" \
        : "=r"((r)[0]), "=r"((r)[1]), "=r"((r)[2]), "=r"((r)[3]) : "r"(addr))

#define MMA_BF16(d, a, br0, br1) \
    asm volatile("mma.sync.aligned.m16n8k16.row.col.f32.bf16.bf16.f32 " \
        "{%0,%1,%2,%3}, {%4,%5,%6,%7}, {%8,%9}, {%0,%1,%2,%3};" \
        : "+f"((d)[0]), "+f"((d)[1]), "+f"((d)[2]), "+f"((d)[3]) \
        : "r"((a)[0]), "r"((a)[1]), "r"((a)[2]), "r"((a)[3]), "r"(br0), "r"(br1))

// pack two f32 -> bf16x2 (lo = x0, hi = x1)
#define PACK_BF16X2(res, x0, x1) \
    asm("cvt.rn.bf16x2.f32 %0, %1, %2;" : "=r"(res) : "f"(x1), "f"(x0))

// ---------------------------------------------------------------------------
// Split fp32 [R, 1024] -> bf16 [R, 3072]:
// A operand: hi @0, hi @1024, lo @2048   -> A' = [hi|hi|lo]
// B operand: hi @0, lo @1024, hi @2048   -> B' = [hi|lo|hi]
// A'.B'^T = hi.hi + hi.lo + lo.hi  (lo.lo term ~2^-18, dropped)
// ---------------------------------------------------------------------------
__global__ __launch_bounds__(256) void split_kernel(
    const float* __restrict__ src, __nv_bfloat16* __restrict__ dst,
    int hi2_off, int lo_off)
{
    int idx = blockIdx.x * blockDim.x + threadIdx.x;
    int row = idx >> 7;            // K/8 = 128 chunks per row
    int c8  = (idx & 127) << 3;

    const float* p = src + (size_t)row * CDIM + c8;
    float4 v0 = *(const float4*)p;
    float4 v1 = *(const float4*)(p + 4);
    float xs[8] = {v0.x, v0.y, v0.z, v0.w, v1.x, v1.y, v1.z, v1.w};

    uint32_t hv[4], lv[4];
    #pragma unroll
    for (int i = 0; i < 4; i++) {
        float x0 = xs[2*i], x1 = xs[2*i + 1];
        uint32_t ph; PACK_BF16X2(ph, x0, x1);
        float h0 = __uint_as_float(ph << 16);
        float h1 = __uint_as_float(ph & 0xffff0000u);
        uint32_t pl; PACK_BF16X2(pl, x0 - h0, x1 - h1);
        hv[i] = ph; lv[i] = pl;
    }
    uint4 hq = make_uint4(hv[0], hv[1], hv[2], hv[3]);
    uint4 lq = make_uint4(lv[0], lv[1], lv[2], lv[3]);

    __nv_bfloat16* base = dst + (size_t)row * K3;
    *reinterpret_cast<uint4*>(base + c8)           = hq;
    *reinterpret_cast<uint4*>(base + hi2_off + c8) = hq;
    *reinterpret_cast<uint4*>(base + lo_off  + c8) = lq;
}

// ---------------------------------------------------------------------------
// Pre-split K/V tiles into smem-image blocks for verbatim cp.async.
// ---------------------------------------------------------------------------
__global__ __launch_bounds__(256) void presplit_kv_kernel(
    const float* __restrict__ qkv, char* __restrict__ ksp, char* __restrict__ vsp)
{
    const int tid = threadIdx.x;
    const int kt = blockIdx.x, h = blockIdx.y, b = blockIdx.z;
    size_t blk = ((size_t)((b * NH + h) * NKT + kt)) * 16384;
    char* kh = ksp + blk; char* kl = kh + 8192;
    char* vh = vsp + blk; char* vl = vh + 8192;
    const float* base = qkv + (size_t)(b * TSEQ + kt * 64) * 3072 + h * 64;

    for (int u = tid; u < 1024; u += 256) {
        int isV = u >> 9;
        int uu  = u & 511;
        int row = uu >> 3;
        int c8  = (uu & 7) * 8;
        const float* p = base + (size_t)row * 3072 + (isV ? 2048 : 1024) + c8;
        float4 v0 = *(const float4*)p;
        float4 v1 = *(const float4*)(p + 4);
        float xs[8] = {v0.x, v0.y, v0.z, v0.w, v1.x, v1.y, v1.z, v1.w};
        uint32_t hv[4], lv[4];
        #pragma unroll
        for (int i = 0; i < 4; i++) {
            float x0 = xs[2*i], x1 = xs[2*i + 1];
            uint32_t ph; PACK_BF16X2(ph, x0, x1);
            float h0 = __uint_as_float(ph << 16);
            float h1 = __uint_as_float(ph & 0xffff0000u);
            uint32_t pl; PACK_BF16X2(pl, x0 - h0, x1 - h1);
            hv[i] = ph; lv[i] = pl;
        }
        uint32_t off = row * 128 + ((uint32_t)(c8 * 2) ^ ((row & 7) << 4));
        char* dh = isV ? vh : kh;
        char* dl = isV ? vl : kl;
        *(uint4*)(dh + off) = make_uint4(hv[0], hv[1], hv[2], hv[3]);
        *(uint4*)(dl + off) = make_uint4(lv[0], lv[1], lv[2], lv[3]);
    }
}

// ---------------------------------------------------------------------------
// bf16 NT GEMM via mma.sync (HMMA): Round-6 proven shape (128x128, 64x32 warp
// tile, 122 regs, 2 CTAs/SM) with pipeline deepened to 3 cp.async stages.
// ---------------------------------------------------------------------------
#define GSTAGE 32768           // A 16KB + B 16KB per stage
#define GEMM_SMEM (3 * GSTAGE) // 98304

__global__ __launch_bounds__(256) void gemm_bf16_kernel(
    const __nv_bfloat16* __restrict__ A, const __nv_bfloat16* __restrict__ B,
    const float* __restrict__ bias, float* __restrict__ C,
    int M, int N, int K)
{
    extern __shared__ char sm[];
    uint32_t smb = smem_u32(sm);
    const int tid  = threadIdx.x;
    const int lane = tid & 31;
    const int wid  = tid >> 5;
    const int wm   = wid >> 2;        // 0..1
    const int wn   = wid & 3;         // 0..3
    const int m0   = blockIdx.y * 128;
    const int n0   = blockIdx.x * 128;
    const int NK   = K >> 6;

    const size_t Kb = (size_t)K * 2;
    const char* Abase = (const char*)A + (size_t)m0 * Kb;
    const char* Bbase = (const char*)B + (size_t)n0 * Kb;

    const int lr = tid >> 3;
    const int lc = (tid & 7) << 4;

    float acc[4][4][4];
    #pragma unroll
    for (int i = 0; i < 4; i++)
        #pragma unroll
        for (int j = 0; j < 4; j++)
            #pragma unroll
            for (int r = 0; r < 4; r++) acc[i][j][r] = 0.f;

    const int lrow  = lane & 15;
    const int lhalf = (lane >> 4) << 4;
    uint32_t arow[4], axor[4], brow[2], bxor[2];
    #pragma unroll
    for (int mi = 0; mi < 4; mi++) {
        int r = wm * 64 + mi * 16 + lrow;
        arow[mi] = r * 128; axor[mi] = (r & 7) << 4;
    }
    #pragma unroll
    for (int bi = 0; bi < 2; bi++) {
        int r = wn * 32 + bi * 16 + lrow;
        brow[bi] = r * 128; bxor[bi] = (r & 7) << 4;
    }

    auto load_stage = [&](int kt, int s) {
        uint32_t sa = smb + s * GSTAGE;
        uint32_t sb = sa + 16384;
        size_t ktb = (size_t)kt << 7;
        #pragma unroll
        for (int p = 0; p < 4; p++) {
            int row = lr + p * 32;
            uint32_t so = row * 128 + (lc ^ ((row & 7) << 4));
            CPASYNC16(sa + so, Abase + (size_t)row * Kb + ktb + lc);
            CPASYNC16(sb + so, Bbase + (size_t)row * Kb + ktb + lc);
        }
    };

    load_stage(0, 0); CPASYNC_COMMIT();
    load_stage(1, 1); CPASYNC_COMMIT();
    load_stage(2, 2); CPASYNC_COMMIT();

    int slot = 0;
    for (int kt = 0; kt < NK; kt++) {
        CPASYNC_WAIT2();
        __syncthreads();
        uint32_t sa = smb + slot * GSTAGE;
        uint32_t sb = sa + 16384;

        #pragma unroll
        for (int ks = 0; ks < 4; ks++) {
            uint32_t kb = (ks << 5) + lhalf;
            uint32_t a[4][4], b[2][4];
            #pragma unroll
            for (int mi = 0; mi < 4; mi++)
                LDSM_X4(a[mi], sa + arow[mi] + (kb ^ axor[mi]));
            #pragma unroll
            for (int bi = 0; bi < 2; bi++)
                LDSM_X4(b[bi], sb + brow[bi] + (kb ^ bxor[bi]));
            #pragma unroll
            for (int mi = 0; mi < 4; mi++)
                #pragma unroll
                for (int ni = 0; ni < 4; ni++)
                    MMA_BF16(acc[mi][ni], a[mi],
                             b[ni >> 1][ni & 1], b[ni >> 1][(ni & 1) + 2]);
        }
        __syncthreads();
        if (kt + 3 < NK) load_stage(kt + 3, slot);
        CPASYNC_COMMIT();
        slot = (slot == 2) ? 0 : slot + 1;
    }

    const int g  = lane >> 2;
    const int tg = (lane & 3) << 1;
    #pragma unroll
    for (int mi = 0; mi < 4; mi++) {
        int r0 = m0 + wm * 64 + mi * 16 + g;
        #pragma unroll
        for (int ni = 0; ni < 4; ni++) {
            int col = n0 + wn * 32 + ni * 8 + tg;
            float b0 = bias[col], b1 = bias[col + 1];
            float2 v0 = {acc[mi][ni][0] + b0, acc[mi][ni][1] + b1};
            float2 v1 = {acc[mi][ni][2] + b0, acc[mi][ni][3] + b1};
            *(float2*)&C[(size_t)r0 * N + col] = v0;
            *(float2*)&C[(size_t)(r0 + 8) * N + col] = v1;
        }
    }
}

// ---------------------------------------------------------------------------
// Flash attention via HMMA, bf16 hi/lo split, causal. Fused split epilogue:
// writes the attention output DIRECTLY in split [hi|hi|lo] layout (g_as).
// ---------------------------------------------------------------------------
#define FSTG 32768
#define FLASH_SMEM (32768 + 2 * FSTG)   // 98304

__global__ __launch_bounds__(256, 1) void flash_hmma_kernel(
    const float* __restrict__ qkv,
    const char* __restrict__ ksp, const char* __restrict__ vsp,
    __nv_bfloat16* __restrict__ outs)
{
    extern __shared__ char sm[];
    uint32_t smb = smem_u32(sm);
    const uint32_t sQh = smb;
    const uint32_t sQl = smb + 16384;
    char* Qh = sm;
    char* Ql = sm + 16384;

    const int tid  = threadIdx.x;
    const int lane = tid & 31;
    const int w    = tid >> 5;
    const int g    = lane >> 2;
    const int t    = lane & 3;
    const int qt   = (gridDim.x - 1) - blockIdx.x;   // heavy tiles first
    const int h    = blockIdx.y;
    const int b    = blockIdx.z;
    const int q0   = qt * 128;

    const float* qbase = qkv + (size_t)(b * TSEQ) * 3072 + h * 64;
    const char* kbh = ksp + ((size_t)((b * NH + h) * NKT)) * 16384;
    const char* vbh = vsp + ((size_t)((b * NH + h) * NKT)) * 16384;

    const int nkt = 2 * qt + 2;

    auto load_stage = [&](int kt2, int s) {
        uint32_t d = smb + 32768 + s * FSTG;
        const char* sk = kbh + (size_t)kt2 * 16384;
        const char* sv = vbh + (size_t)kt2 * 16384;
        #pragma unroll
        for (int i = 0; i < 4; i++) {
            uint32_t o = (uint32_t)(tid + i * 256) * 16;
            CPASYNC16(d + o, sk + o);
            CPASYNC16(d + 16384 + o, sv + o);
        }
    };

    load_stage(0, 0); CPASYNC_COMMIT();
    if (nkt > 1) load_stage(1, 1);
    CPASYNC_COMMIT();

    // ---- Load Q tile (128 x 64 fp32), scale by 0.125, split hi/lo to smem ----
    for (int u = tid; u < 1024; u += 256) {
        int row = u >> 3;
        int c8  = (u & 7) * 8;
        const float* p = qbase + (size_t)(q0 + row) * 3072 + c8;
        float4 v0 = *(const float4*)p;
        float4 v1 = *(const float4*)(p + 4);
        float xs[8] = {v0.x, v0.y, v0.z, v0.w, v1.x, v1.y, v1.z, v1.w};
        uint32_t hv[4], lv[4];
        #pragma unroll
        for (int i = 0; i < 4; i++) {
            float x0 = xs[2*i] * 0.125f, x1 = xs[2*i + 1] * 0.125f;
            uint32_t ph; PACK_BF16X2(ph, x0, x1);
            float h0 = __uint_as_float(ph << 16);
            float h1 = __uint_as_float(ph & 0xffff0000u);
            uint32_t pl; PACK_BF16X2(pl, x0 - h0, x1 - h1);
            hv[i] = ph; lv[i] = pl;
        }
        uint32_t off = row * 128 + ((uint32_t)(c8 * 2) ^ ((row & 7) << 4));
        *(uint4*)(Qh + off) = make_uint4(hv[0], hv[1], hv[2], hv[3]);
        *(uint4*)(Ql + off) = make_uint4(lv[0], lv[1], lv[2], lv[3]);
    }

    const int lrow  = lane & 15;
    const int lhalf = (lane >> 4) << 4;
    const uint32_t aoff = (uint32_t)((w * 16 + lrow) * 128);
    const uint32_t axor = (uint32_t)((lrow & 7) << 4);
    const uint32_t kxor = axor;

    float o[8][4];
    #pragma unroll
    for (int i = 0; i < 8; i++)
        #pragma unroll
        for (int j = 0; j < 4; j++) o[i][j] = 0.f;
    float m0 = -1e30f, m1 = -1e30f, l0 = 0.f, l1 = 0.f;
    const int qw = q0 + w * 16;

    for (int kt = 0; kt < nkt; kt++) {
        const int k0 = kt * 64;
        CPASYNC_WAIT1();
        __syncthreads();
        const uint32_t sKh = smb + 32768 + (kt & 1) * FSTG;
        const uint32_t sKl = sKh + 8192;
        const uint32_t sVh = sKh + 16384;
        const uint32_t sVl = sKh + 24576;

        float s[8][4];
        #pragma unroll
        for (int i = 0; i < 8; i++)
            #pragma unroll
            for (int j = 0; j < 4; j++) s[i][j] = 0.f;

        #pragma unroll
        for (int kc = 0; kc < 4; kc++) {
            uint32_t colb = (uint32_t)(kc * 32 + lhalf);
            uint32_t ah[4], al[4];
            LDSM_X4(ah, sQh + aoff + (colb ^ axor));
            LDSM_X4(al, sQl + aoff + (colb ^ axor));
            #pragma unroll
            for (int gk = 0; gk < 4; gk++) {
                uint32_t ro = (uint32_t)((gk * 16 + lrow) * 128);
                uint32_t kh[4], kl[4];
                LDSM_X4(kh, sKh + ro + (colb ^ kxor));
                LDSM_X4(kl, sKl + ro + (colb ^ kxor));
                #pragma unroll
                for (int pp = 0; pp < 2; pp++) {
                    int nt = gk * 2 + pp;
                    MMA_BF16(s[nt], ah, kh[pp], kh[pp + 2]);
                    MMA_BF16(s[nt], ah, kl[pp], kl[pp + 2]);
                    MMA_BF16(s[nt], al, kh[pp], kh[pp + 2]);
                }
            }
        }

        if (k0 + 63 > qw) {
            int r0 = qw + g, r1 = qw + g + 8;
            #pragma unroll
            for (int nt = 0; nt < 8; nt++) {
                int col = k0 + nt * 8 + 2 * t;
                if (col     > r0) s[nt][0] = -1e30f;
                if (col + 1 > r0) s[nt][1] = -1e30f;
                if (col     > r1) s[nt][2] = -1e30f;
                if (col + 1 > r1) s[nt][3] = -1e30f;
            }
        }

        float mx0 = -1e30f, mx1 = -1e30f;
        #pragma unroll
        for (int nt = 0; nt < 8; nt++) {
            mx0 = fmaxf(mx0, fmaxf(s[nt][0], s[nt][1]));
            mx1 = fmaxf(mx1, fmaxf(s[nt][2], s[nt][3]));
        }
        mx0 = fmaxf(mx0, __shfl_xor_sync(0xffffffffu, mx0, 1));
        mx0 = fmaxf(mx0, __shfl_xor_sync(0xffffffffu, mx0, 2));
        mx1 = fmaxf(mx1, __shfl_xor_sync(0xffffffffu, mx1, 1));
        mx1 = fmaxf(mx1, __shfl_xor_sync(0xffffffffu, mx1, 2));
        float mn0 = fmaxf(m0, mx0), mn1 = fmaxf(m1, mx1);
        float c0 = __expf(m0 - mn0), c1 = __expf(m1 - mn1);
        float sum0 = 0.f, sum1 = 0.f;
        #pragma unroll
        for (int nt = 0; nt < 8; nt++) {
            s[nt][0] = __expf(s[nt][0] - mn0);
            s[nt][1] = __expf(s[nt][1] - mn0);
            s[nt][2] = __expf(s[nt][2] - mn1);
            s[nt][3] = __expf(s[nt][3] - mn1);
            sum0 += s[nt][0] + s[nt][1];
            sum1 += s[nt][2] + s[nt][3];
        }
        sum0 += __shfl_xor_sync(0xffffffffu, sum0, 1);
        sum0 += __shfl_xor_sync(0xffffffffu, sum0, 2);
        sum1 += __shfl_xor_sync(0xffffffffu, sum1, 1);
        sum1 += __shfl_xor_sync(0xffffffffu, sum1, 2);
        l0 = l0 * c0 + sum0; l1 = l1 * c1 + sum1;
        m0 = mn0; m1 = mn1;
        #pragma unroll
        for (int nt = 0; nt < 8; nt++) {
            o[nt][0] *= c0; o[nt][1] *= c0;
            o[nt][2] *= c1; o[nt][3] *= c1;
        }

        uint32_t ph[16], pl[16];
        #pragma unroll
        for (int c2 = 0; c2 < 8; c2++) {
            int ib = (c2 >> 1) * 4 + (c2 & 1) * 2;
            uint32_t p01, p23;
            PACK_BF16X2(p01, s[c2][0], s[c2][1]);
            PACK_BF16X2(p23, s[c2][2], s[c2][3]);
            float h0 = __uint_as_float(p01 << 16);
            float h1 = __uint_as_float(p01 & 0xffff0000u);
            float h2 = __uint_as_float(p23 << 16);
            float h3 = __uint_as_float(p23 & 0xffff0000u);
            uint32_t q01, q23;
            PACK_BF16X2(q01, s[c2][0] - h0, s[c2][1] - h1);
            PACK_BF16X2(q23, s[c2][2] - h2, s[c2][3] - h3);
            ph[ib] = p01; ph[ib + 1] = p23;
            pl[ib] = q01; pl[ib + 1] = q23;
        }

        #pragma unroll
        for (int kc = 0; kc < 4; kc++) {
            const uint32_t* aH = &ph[kc * 4];
            const uint32_t* aL = &pl[kc * 4];
            uint32_t ro = (uint32_t)((kc * 16 + lrow) * 128);
            #pragma unroll
            for (int j = 0; j < 4; j++) {
                uint32_t cb = ((uint32_t)(j * 32 + lhalf)) ^ kxor;
                uint32_t vh[4], vl[4];
                LDSM_X4_T(vh, sVh + ro + cb);
                LDSM_X4_T(vl, sVl + ro + cb);
                MMA_BF16(o[2*j],     aH, vh[0], vh[1]);
                MMA_BF16(o[2*j + 1], aH, vh[2], vh[3]);
                MMA_BF16(o[2*j],     aH, vl[0], vl[1]);
                MMA_BF16(o[2*j + 1], aH, vl[2], vl[3]);
                MMA_BF16(o[2*j],     aL, vh[0], vh[1]);
                MMA_BF16(o[2*j + 1], aL, vh[2], vh[3]);
            }
        }

        __syncthreads();
        if (kt + 2 < nkt) load_stage(kt + 2, kt & 1);
        CPASYNC_COMMIT();
    }

    // ---- finalize: O /= l, write split bf16 [hi|hi|lo] rows of g_as ----
    float inv0 = 1.0f / l0, inv1 = 1.0f / l1;
    int r0 = qw + g, r1 = qw + g + 8;
    __nv_bfloat16* ab = outs + (size_t)(b * TSEQ) * K3 + h * 64;
    uint32_t* p0 = (uint32_t*)(ab + (size_t)r0 * K3);
    uint32_t* p1 = (uint32_t*)(ab + (size_t)r1 * K3);
    #pragma unroll
    for (int nt = 0; nt < 8; nt++) {
        int c2 = (nt * 8 + 2 * t) >> 1;      // uint32 index within row
        float y00 = o[nt][0] * inv0, y01 = o[nt][1] * inv0;
        float y10 = o[nt][2] * inv1, y11 = o[nt][3] * inv1;
        uint32_t h0p, h1p;
        PACK_BF16X2(h0p, y00, y01);
        PACK_BF16X2(h1p, y10, y11);
        float a0 = __uint_as_float(h0p << 16);
        float a1 = __uint_as_float(h0p & 0xffff0000u);
        float b0 = __uint_as_float(h1p << 16);
        float b1 = __uint_as_float(h1p & 0xffff0000u);
        uint32_t l0p, l1p;
        PACK_BF16X2(l0p, y00 - a0, y01 - a1);
        PACK_BF16X2(l1p, y10 - b0, y11 - b1);
        p0[c2] = h0p; p0[c2 + 512] = h0p; p0[c2 + 1024] = l0p;
        p1[c2] = h1p; p1[c2 + 512] = h1p; p1[c2 + 1024] = l1p;
    }
}

// ---------------------------------------------------------------------------
// Launch
// ---------------------------------------------------------------------------
extern "C" void kernel_launch(void* const* d_in, const int* in_sizes, int n_in,
                              void* d_out, int out_size)
{
    const float* x      = (const float*)d_in[0];
    const float* W_qkv  = (const float*)d_in[1];
    const float* b_qkv  = (const float*)d_in[2];
    const float* W_proj = (const float*)d_in[3];
    const float* b_proj = (const float*)d_in[4];
    float* out = (float*)d_out;

    float *qkv;
    __nv_bfloat16 *xs, *as, *wqs, *wps;
    char *ksp, *vsp;
    cudaGetSymbolAddress((void**)&qkv, g_qkv);
    cudaGetSymbolAddress((void**)&xs,  g_xs);
    cudaGetSymbolAddress((void**)&as,  g_as);
    cudaGetSymbolAddress((void**)&wqs, g_wqs);
    cudaGetSymbolAddress((void**)&wps, g_wps);
    cudaGetSymbolAddress((void**)&ksp, g_ksp);
    cudaGetSymbolAddress((void**)&vsp, g_vsp);

    cudaFuncSetAttribute(gemm_bf16_kernel,
                         cudaFuncAttributeMaxDynamicSharedMemorySize, GEMM_SMEM);
    cudaFuncSetAttribute(flash_hmma_kernel,
                         cudaFuncAttributeMaxDynamicSharedMemorySize, FLASH_SMEM);

    // Splits: A operands [hi|hi|lo], B operands [hi|lo|hi]
    split_kernel<<<BT * CDIM / 8 / 256, 256>>>(x, xs, CDIM, 2 * CDIM);
    split_kernel<<<3 * CDIM * CDIM / 8 / 256, 256>>>(W_qkv, wqs, 2 * CDIM, CDIM);
    split_kernel<<<CDIM * CDIM / 8 / 256, 256>>>(W_proj, wps, 2 * CDIM, CDIM);

    // 1) QKV projection (tensor cores, split-K', 128x128 tiles, 3-stage)
    gemm_bf16_kernel<<<dim3(3 * CDIM / 128, BT / 128), 256, GEMM_SMEM>>>(
        xs, wqs, b_qkv, qkv, BT, 3 * CDIM, K3);

    // 1b) Pre-split K/V into smem-image blocks
    presplit_kv_kernel<<<dim3(NKT, NH, BATCH), 256>>>(qkv, ksp, vsp);

    // 2) Causal flash attention (HMMA, split); writes att directly in split form
    flash_hmma_kernel<<<dim3(TSEQ / 128, NH, BATCH), 256, FLASH_SMEM>>>(
        qkv, ksp, vsp, as);

    // 3) Output projection (128x128 tiles, 3-stage)
    gemm_bf16_kernel<<<dim3(CDIM / 128, BT / 128), 256, GEMM_SMEM>>>(
        as, wps, b_proj, out, BT, CDIM, K3);
}

// round 9
// speedup vs baseline: 1.1135x; 1.0534x over previous
#include <cuda_runtime.h>
#include <cuda_bf16.h>
#include <cstdint>
#include <math.h>

#define BATCH 4
#define TSEQ  2048
#define CDIM  1024
#define NH    16
#define HD    64
#define BT    (BATCH * TSEQ)
#define K3    (3 * CDIM)          // split-extended K dimension = 3072
#define NKT   (TSEQ / 64)         // 32 key tiles per (b,h)
#define NQT   (TSEQ / 128)        // 16 query tiles per (b,h)

// ---------------------------------------------------------------------------
// Scratch (__device__ globals; no allocation allowed)
// ---------------------------------------------------------------------------
__device__ __nv_bfloat16 g_xs[(size_t)BT * K3];            // x split  [hi|hi|lo]
__device__ __nv_bfloat16 g_as[(size_t)BT * K3];            // att split[hi|hi|lo]
__device__ __nv_bfloat16 g_wqs[(size_t)3 * CDIM * K3];     // W_qkv    [hi|lo|hi]
__device__ __nv_bfloat16 g_wps[(size_t)CDIM * K3];         // W_proj   [hi|lo|hi]
// Split Q: per (b,h,qt128) 32KB block = [hi 16KB | lo 16KB], smem-layout bytes
__device__ char g_qs[(size_t)BATCH * NH * NQT * 32768];
// Split K/V: per (b,h,kt64) 16KB block = [hi 8KB | lo 8KB], smem-layout bytes
__device__ char g_ksp[(size_t)BATCH * NH * NKT * 16384];
__device__ char g_vsp[(size_t)BATCH * NH * NKT * 16384];

// ---------------------------------------------------------------------------
// PTX helpers (sm_100-baseline safe: cp.async + ldmatrix + mma.sync only)
// ---------------------------------------------------------------------------
__device__ __forceinline__ uint32_t smem_u32(const void* p) {
    uint32_t a;
    asm("{ .reg .u64 t; cvta.to.shared.u64 t, %1; cvt.u32.u64 %0, t; }"
        : "=r"(a) : "l"(p));
    return a;
}

#define CPASYNC16(dst, src) \
    asm volatile("cp.async.cg.shared.global [%0], [%1], 16;" \
        :: "r"(dst), "l"(src))
#define CPASYNC_COMMIT() asm volatile("cp.async.commit_group;")
#define CPASYNC_WAIT1()  asm volatile("cp.async.wait_group 1;")
#define CPASYNC_WAIT2()  asm volatile("cp.async.wait_group 2;")

#define LDSM_X4(r, addr) \
    asm volatile("ldmatrix.sync.aligned.m8n8.x4.shared.b16 {%0,%1,%2,%3}, [%4];" \
        : "=r"((r)[0]), "=r"((r)[1]), "=r"((r)[2]), "=r"((r)[3]) : "r"(addr))

#define LDSM_X4_T(r, addr) \
    asm volatile("ldmatrix.sync.aligned.m8n8.x4.trans.shared.b16 {%0,%1,%2,%3}, [%4];" \
        : "=r"((r)[0]), "=r"((r)[1]), "=r"((r)[2]), "=r"((r)[3]) : "r"(addr))

#define MMA_BF16(d, a, br0, br1) \
    asm volatile("mma.sync.aligned.m16n8k16.row.col.f32.bf16.bf16.f32 " \
        "{%0,%1,%2,%3}, {%4,%5,%6,%7}, {%8,%9}, {%0,%1,%2,%3};" \
        : "+f"((d)[0]), "+f"((d)[1]), "+f"((d)[2]), "+f"((d)[3]) \
        : "r"((a)[0]), "r"((a)[1]), "r"((a)[2]), "r"((a)[3]), "r"(br0), "r"(br1))

// pack two f32 -> bf16x2 (lo = x0, hi = x1)
#define PACK_BF16X2(res, x0, x1) \
    asm("cvt.rn.bf16x2.f32 %0, %1, %2;" : "=r"(res) : "f"(x1), "f"(x0))

// ---------------------------------------------------------------------------
// Split fp32 [R, 1024] -> bf16 [R, 3072]:
// A operand: hi @0, hi @1024, lo @2048   -> A' = [hi|hi|lo]
// B operand: hi @0, lo @1024, hi @2048   -> B' = [hi|lo|hi]
// A'.B'^T = hi.hi + hi.lo + lo.hi  (lo.lo term ~2^-18, dropped)
// ---------------------------------------------------------------------------
__global__ __launch_bounds__(256) void split_kernel(
    const float* __restrict__ src, __nv_bfloat16* __restrict__ dst,
    int hi2_off, int lo_off)
{
    int idx = blockIdx.x * blockDim.x + threadIdx.x;
    int row = idx >> 7;            // K/8 = 128 chunks per row
    int c8  = (idx & 127) << 3;

    const float* p = src + (size_t)row * CDIM + c8;
    float4 v0 = *(const float4*)p;
    float4 v1 = *(const float4*)(p + 4);
    float xs[8] = {v0.x, v0.y, v0.z, v0.w, v1.x, v1.y, v1.z, v1.w};

    uint32_t hv[4], lv[4];
    #pragma unroll
    for (int i = 0; i < 4; i++) {
        float x0 = xs[2*i], x1 = xs[2*i + 1];
        uint32_t ph; PACK_BF16X2(ph, x0, x1);
        float h0 = __uint_as_float(ph << 16);
        float h1 = __uint_as_float(ph & 0xffff0000u);
        uint32_t pl; PACK_BF16X2(pl, x0 - h0, x1 - h1);
        hv[i] = ph; lv[i] = pl;
    }
    uint4 hq = make_uint4(hv[0], hv[1], hv[2], hv[3]);
    uint4 lq = make_uint4(lv[0], lv[1], lv[2], lv[3]);

    __nv_bfloat16* base = dst + (size_t)row * K3;
    *reinterpret_cast<uint4*>(base + c8)           = hq;
    *reinterpret_cast<uint4*>(base + hi2_off + c8) = hq;
    *reinterpret_cast<uint4*>(base + lo_off  + c8) = lq;
}

// ---------------------------------------------------------------------------
// bf16 NT GEMM via mma.sync (HMMA), 128x128 tile, 64x32 warp tile, 3-stage.
// mode 0: C = A.B^T + bias (fp32 store).
// mode 1 (QKV): epilogue splits outputs hi/lo and scatters into smem-image
//   blocks: Q (scaled 0.125) -> qs, K -> ksp, V -> vsp. No fp32 intermediate.
// ---------------------------------------------------------------------------
#define GSTAGE 32768           // A 16KB + B 16KB per stage
#define GEMM_SMEM (3 * GSTAGE) // 98304

__global__ __launch_bounds__(256) void gemm_bf16_kernel(
    const __nv_bfloat16* __restrict__ A, const __nv_bfloat16* __restrict__ B,
    const float* __restrict__ bias, float* __restrict__ C,
    int M, int N, int K,
    char* __restrict__ qs, char* __restrict__ ksp, char* __restrict__ vsp,
    int mode)
{
    extern __shared__ char sm[];
    uint32_t smb = smem_u32(sm);
    const int tid  = threadIdx.x;
    const int lane = tid & 31;
    const int wid  = tid >> 5;
    const int wm   = wid >> 2;        // 0..1
    const int wn   = wid & 3;         // 0..3
    const int m0   = blockIdx.y * 128;
    const int n0   = blockIdx.x * 128;
    const int NK   = K >> 6;

    const size_t Kb = (size_t)K * 2;
    const char* Abase = (const char*)A + (size_t)m0 * Kb;
    const char* Bbase = (const char*)B + (size_t)n0 * Kb;

    const int lr = tid >> 3;
    const int lc = (tid & 7) << 4;

    float acc[4][4][4];
    #pragma unroll
    for (int i = 0; i < 4; i++)
        #pragma unroll
        for (int j = 0; j < 4; j++)
            #pragma unroll
            for (int r = 0; r < 4; r++) acc[i][j][r] = 0.f;

    const int lrow  = lane & 15;
    const int lhalf = (lane >> 4) << 4;
    uint32_t arow[4], axor[4], brow[2], bxor[2];
    #pragma unroll
    for (int mi = 0; mi < 4; mi++) {
        int r = wm * 64 + mi * 16 + lrow;
        arow[mi] = r * 128; axor[mi] = (r & 7) << 4;
    }
    #pragma unroll
    for (int bi = 0; bi < 2; bi++) {
        int r = wn * 32 + bi * 16 + lrow;
        brow[bi] = r * 128; bxor[bi] = (r & 7) << 4;
    }

    auto load_stage = [&](int kt, int s) {
        uint32_t sa = smb + s * GSTAGE;
        uint32_t sb = sa + 16384;
        size_t ktb = (size_t)kt << 7;
        #pragma unroll
        for (int p = 0; p < 4; p++) {
            int row = lr + p * 32;
            uint32_t so = row * 128 + (lc ^ ((row & 7) << 4));
            CPASYNC16(sa + so, Abase + (size_t)row * Kb + ktb + lc);
            CPASYNC16(sb + so, Bbase + (size_t)row * Kb + ktb + lc);
        }
    };

    load_stage(0, 0); CPASYNC_COMMIT();
    load_stage(1, 1); CPASYNC_COMMIT();
    load_stage(2, 2); CPASYNC_COMMIT();

    int slot = 0;
    for (int kt = 0; kt < NK; kt++) {
        CPASYNC_WAIT2();
        __syncthreads();
        uint32_t sa = smb + slot * GSTAGE;
        uint32_t sb = sa + 16384;

        #pragma unroll
        for (int ks = 0; ks < 4; ks++) {
            uint32_t kb = (ks << 5) + lhalf;
            uint32_t a[4][4], b[2][4];
            #pragma unroll
            for (int mi = 0; mi < 4; mi++)
                LDSM_X4(a[mi], sa + arow[mi] + (kb ^ axor[mi]));
            #pragma unroll
            for (int bi = 0; bi < 2; bi++)
                LDSM_X4(b[bi], sb + brow[bi] + (kb ^ bxor[bi]));
            #pragma unroll
            for (int mi = 0; mi < 4; mi++)
                #pragma unroll
                for (int ni = 0; ni < 4; ni++)
                    MMA_BF16(acc[mi][ni], a[mi],
                             b[ni >> 1][ni & 1], b[ni >> 1][(ni & 1) + 2]);
        }
        __syncthreads();
        if (kt + 3 < NK) load_stage(kt + 3, slot);
        CPASYNC_COMMIT();
        slot = (slot == 2) ? 0 : slot + 1;
    }

    const int g  = lane >> 2;
    const int tg = (lane & 3) << 1;

    if (mode == 0) {
        #pragma unroll
        for (int mi = 0; mi < 4; mi++) {
            int r0 = m0 + wm * 64 + mi * 16 + g;
            #pragma unroll
            for (int ni = 0; ni < 4; ni++) {
                int col = n0 + wn * 32 + ni * 8 + tg;
                float b0 = bias[col], b1 = bias[col + 1];
                float2 v0 = {acc[mi][ni][0] + b0, acc[mi][ni][1] + b1};
                float2 v1 = {acc[mi][ni][2] + b0, acc[mi][ni][3] + b1};
                *(float2*)&C[(size_t)r0 * N + col] = v0;
                *(float2*)&C[(size_t)(r0 + 8) * N + col] = v1;
            }
        }
    } else {
        // QKV split epilogue. Region uniform per CTA (n tiles 1024-aligned).
        const int region = n0 >> 10;       // 0=Q, 1=K, 2=V
        const int ncol0  = n0 & 1023;
        #pragma unroll
        for (int mi = 0; mi < 4; mi++) {
            #pragma unroll
            for (int rr = 0; rr < 2; rr++) {
                int trow = m0 + wm * 64 + mi * 16 + g + rr * 8;
                int bb   = trow >> 11;          // batch
                int tloc = trow & 2047;         // token within batch
                #pragma unroll
                for (int ni = 0; ni < 4; ni++) {
                    int gcol = n0 + wn * 32 + ni * 8 + tg;
                    int colr = ncol0 + wn * 32 + ni * 8 + tg;
                    int h = colr >> 6;
                    int d = colr & 63;
                    float y0 = acc[mi][ni][rr * 2 + 0] + bias[gcol];
                    float y1 = acc[mi][ni][rr * 2 + 1] + bias[gcol + 1];
                    if (region == 0) { y0 *= 0.125f; y1 *= 0.125f; }
                    uint32_t hp; PACK_BF16X2(hp, y0, y1);
                    float h0 = __uint_as_float(hp << 16);
                    float h1 = __uint_as_float(hp & 0xffff0000u);
                    uint32_t lp; PACK_BF16X2(lp, y0 - h0, y1 - h1);
                    if (region == 0) {
                        char* blk = qs +
                            ((size_t)((bb * NH + h) * NQT + (tloc >> 7))) * 32768;
                        int rowb = tloc & 127;
                        uint32_t off = rowb * 128 +
                            (((uint32_t)(d * 2)) ^ ((rowb & 7) << 4));
                        *(uint32_t*)(blk + off)         = hp;
                        *(uint32_t*)(blk + 16384 + off) = lp;
                    } else {
                        char* blk = (region == 1 ? ksp : vsp) +
                            ((size_t)((bb * NH + h) * NKT + (tloc >> 6))) * 16384;
                        int rowb = tloc & 63;
                        uint32_t off = rowb * 128 +
                            (((uint32_t)(d * 2)) ^ ((rowb & 7) << 4));
                        *(uint32_t*)(blk + off)        = hp;
                        *(uint32_t*)(blk + 8192 + off) = lp;
                    }
                }
            }
        }
    }
}

// ---------------------------------------------------------------------------
// Flash attention via HMMA, bf16 hi/lo split, causal.
// Q/K/V all pre-split in GMEM smem-image blocks -> verbatim cp.async only.
// Fused epilogue writes attention output in split [hi|hi|lo] layout (g_as).
// ---------------------------------------------------------------------------
#define FSTG 32768
#define FLASH_SMEM (32768 + 2 * FSTG)   // 98304

__global__ __launch_bounds__(256, 1) void flash_hmma_kernel(
    const char* __restrict__ qs,
    const char* __restrict__ ksp, const char* __restrict__ vsp,
    __nv_bfloat16* __restrict__ outs)
{
    extern __shared__ char sm[];
    uint32_t smb = smem_u32(sm);
    const uint32_t sQh = smb;
    const uint32_t sQl = smb + 16384;

    const int tid  = threadIdx.x;
    const int lane = tid & 31;
    const int w    = tid >> 5;
    const int g    = lane >> 2;
    const int t    = lane & 3;
    const int qt   = (gridDim.x - 1) - blockIdx.x;   // heavy tiles first
    const int h    = blockIdx.y;
    const int b    = blockIdx.z;
    const int q0   = qt * 128;

    const char* qblk = qs + ((size_t)((b * NH + h) * NQT + qt)) * 32768;
    const char* kbh = ksp + ((size_t)((b * NH + h) * NKT)) * 16384;
    const char* vbh = vsp + ((size_t)((b * NH + h) * NKT)) * 16384;

    const int nkt = 2 * qt + 2;

    auto load_stage = [&](int kt2, int s) {
        uint32_t d = smb + 32768 + s * FSTG;
        const char* sk = kbh + (size_t)kt2 * 16384;
        const char* sv = vbh + (size_t)kt2 * 16384;
        #pragma unroll
        for (int i = 0; i < 4; i++) {
            uint32_t o = (uint32_t)(tid + i * 256) * 16;
            CPASYNC16(d + o, sk + o);
            CPASYNC16(d + 16384 + o, sv + o);
        }
    };

    // Q (32KB verbatim) + stage 0 in commit-group 0
    #pragma unroll
    for (int i = 0; i < 8; i++) {
        uint32_t o = (uint32_t)(tid + i * 256) * 16;
        CPASYNC16(smb + o, qblk + o);
    }
    load_stage(0, 0); CPASYNC_COMMIT();
    if (nkt > 1) load_stage(1, 1);
    CPASYNC_COMMIT();

    const int lrow  = lane & 15;
    const int lhalf = (lane >> 4) << 4;
    const uint32_t aoff = (uint32_t)((w * 16 + lrow) * 128);
    const uint32_t axor = (uint32_t)((lrow & 7) << 4);
    const uint32_t kxor = axor;

    float o[8][4];
    #pragma unroll
    for (int i = 0; i < 8; i++)
        #pragma unroll
        for (int j = 0; j < 4; j++) o[i][j] = 0.f;
    float m0 = -1e30f, m1 = -1e30f, l0 = 0.f, l1 = 0.f;
    const int qw = q0 + w * 16;

    for (int kt = 0; kt < nkt; kt++) {
        const int k0 = kt * 64;
        CPASYNC_WAIT1();
        __syncthreads();
        const uint32_t sKh = smb + 32768 + (kt & 1) * FSTG;
        const uint32_t sKl = sKh + 8192;
        const uint32_t sVh = sKh + 16384;
        const uint32_t sVl = sKh + 24576;

        float s[8][4];
        #pragma unroll
        for (int i = 0; i < 8; i++)
            #pragma unroll
            for (int j = 0; j < 4; j++) s[i][j] = 0.f;

        #pragma unroll
        for (int kc = 0; kc < 4; kc++) {
            uint32_t colb = (uint32_t)(kc * 32 + lhalf);
            uint32_t ah[4], al[4];
            LDSM_X4(ah, sQh + aoff + (colb ^ axor));
            LDSM_X4(al, sQl + aoff + (colb ^ axor));
            #pragma unroll
            for (int gk = 0; gk < 4; gk++) {
                uint32_t ro = (uint32_t)((gk * 16 + lrow) * 128);
                uint32_t kh[4], kl[4];
                LDSM_X4(kh, sKh + ro + (colb ^ kxor));
                LDSM_X4(kl, sKl + ro + (colb ^ kxor));
                #pragma unroll
                for (int pp = 0; pp < 2; pp++) {
                    int nt = gk * 2 + pp;
                    MMA_BF16(s[nt], ah, kh[pp], kh[pp + 2]);
                    MMA_BF16(s[nt], ah, kl[pp], kl[pp + 2]);
                    MMA_BF16(s[nt], al, kh[pp], kh[pp + 2]);
                }
            }
        }

        if (k0 + 63 > qw) {
            int r0 = qw + g, r1 = qw + g + 8;
            #pragma unroll
            for (int nt = 0; nt < 8; nt++) {
                int col = k0 + nt * 8 + 2 * t;
                if (col     > r0) s[nt][0] = -1e30f;
                if (col + 1 > r0) s[nt][1] = -1e30f;
                if (col     > r1) s[nt][2] = -1e30f;
                if (col + 1 > r1) s[nt][3] = -1e30f;
            }
        }

        float mx0 = -1e30f, mx1 = -1e30f;
        #pragma unroll
        for (int nt = 0; nt < 8; nt++) {
            mx0 = fmaxf(mx0, fmaxf(s[nt][0], s[nt][1]));
            mx1 = fmaxf(mx1, fmaxf(s[nt][2], s[nt][3]));
        }
        mx0 = fmaxf(mx0, __shfl_xor_sync(0xffffffffu, mx0, 1));
        mx0 = fmaxf(mx0, __shfl_xor_sync(0xffffffffu, mx0, 2));
        mx1 = fmaxf(mx1, __shfl_xor_sync(0xffffffffu, mx1, 1));
        mx1 = fmaxf(mx1, __shfl_xor_sync(0xffffffffu, mx1, 2));
        float mn0 = fmaxf(m0, mx0), mn1 = fmaxf(m1, mx1);
        float c0 = __expf(m0 - mn0), c1 = __expf(m1 - mn1);
        float sum0 = 0.f, sum1 = 0.f;
        #pragma unroll
        for (int nt = 0; nt < 8; nt++) {
            s[nt][0] = __expf(s[nt][0] - mn0);
            s[nt][1] = __expf(s[nt][1] - mn0);
            s[nt][2] = __expf(s[nt][2] - mn1);
            s[nt][3] = __expf(s[nt][3] - mn1);
            sum0 += s[nt][0] + s[nt][1];
            sum1 += s[nt][2] + s[nt][3];
        }
        sum0 += __shfl_xor_sync(0xffffffffu, sum0, 1);
        sum0 += __shfl_xor_sync(0xffffffffu, sum0, 2);
        sum1 += __shfl_xor_sync(0xffffffffu, sum1, 1);
        sum1 += __shfl_xor_sync(0xffffffffu, sum1, 2);
        l0 = l0 * c0 + sum0; l1 = l1 * c1 + sum1;
        m0 = mn0; m1 = mn1;
        #pragma unroll
        for (int nt = 0; nt < 8; nt++) {
            o[nt][0] *= c0; o[nt][1] *= c0;
            o[nt][2] *= c1; o[nt][3] *= c1;
        }

        uint32_t ph[16], pl[16];
        #pragma unroll
        for (int c2 = 0; c2 < 8; c2++) {
            int ib = (c2 >> 1) * 4 + (c2 & 1) * 2;
            uint32_t p01, p23;
            PACK_BF16X2(p01, s[c2][0], s[c2][1]);
            PACK_BF16X2(p23, s[c2][2], s[c2][3]);
            float h0 = __uint_as_float(p01 << 16);
            float h1 = __uint_as_float(p01 & 0xffff0000u);
            float h2 = __uint_as_float(p23 << 16);
            float h3 = __uint_as_float(p23 & 0xffff0000u);
            uint32_t q01, q23;
            PACK_BF16X2(q01, s[c2][0] - h0, s[c2][1] - h1);
            PACK_BF16X2(q23, s[c2][2] - h2, s[c2][3] - h3);
            ph[ib] = p01; ph[ib + 1] = p23;
            pl[ib] = q01; pl[ib + 1] = q23;
        }

        #pragma unroll
        for (int kc = 0; kc < 4; kc++) {
            const uint32_t* aH = &ph[kc * 4];
            const uint32_t* aL = &pl[kc * 4];
            uint32_t ro = (uint32_t)((kc * 16 + lrow) * 128);
            #pragma unroll
            for (int j = 0; j < 4; j++) {
                uint32_t cb = ((uint32_t)(j * 32 + lhalf)) ^ kxor;
                uint32_t vh[4], vl[4];
                LDSM_X4_T(vh, sVh + ro + cb);
                LDSM_X4_T(vl, sVl + ro + cb);
                MMA_BF16(o[2*j],     aH, vh[0], vh[1]);
                MMA_BF16(o[2*j + 1], aH, vh[2], vh[3]);
                MMA_BF16(o[2*j],     aH, vl[0], vl[1]);
                MMA_BF16(o[2*j + 1], aH, vl[2], vl[3]);
                MMA_BF16(o[2*j],     aL, vh[0], vh[1]);
                MMA_BF16(o[2*j + 1], aL, vh[2], vh[3]);
            }
        }

        __syncthreads();
        if (kt + 2 < nkt) load_stage(kt + 2, kt & 1);
        CPASYNC_COMMIT();
    }

    // ---- finalize: O /= l, write split bf16 [hi|hi|lo] rows of g_as ----
    float inv0 = 1.0f / l0, inv1 = 1.0f / l1;
    int r0 = qw + g, r1 = qw + g + 8;
    __nv_bfloat16* ab = outs + (size_t)(b * TSEQ) * K3 + h * 64;
    uint32_t* p0 = (uint32_t*)(ab + (size_t)r0 * K3);
    uint32_t* p1 = (uint32_t*)(ab + (size_t)r1 * K3);
    #pragma unroll
    for (int nt = 0; nt < 8; nt++) {
        int c2 = (nt * 8 + 2 * t) >> 1;      // uint32 index within row
        float y00 = o[nt][0] * inv0, y01 = o[nt][1] * inv0;
        float y10 = o[nt][2] * inv1, y11 = o[nt][3] * inv1;
        uint32_t h0p, h1p;
        PACK_BF16X2(h0p, y00, y01);
        PACK_BF16X2(h1p, y10, y11);
        float a0 = __uint_as_float(h0p << 16);
        float a1 = __uint_as_float(h0p & 0xffff0000u);
        float b0 = __uint_as_float(h1p << 16);
        float b1 = __uint_as_float(h1p & 0xffff0000u);
        uint32_t l0p, l1p;
        PACK_BF16X2(l0p, y00 - a0, y01 - a1);
        PACK_BF16X2(l1p, y10 - b0, y11 - b1);
        p0[c2] = h0p; p0[c2 + 512] = h0p; p0[c2 + 1024] = l0p;
        p1[c2] = h1p; p1[c2 + 512] = h1p; p1[c2 + 1024] = l1p;
    }
}

// ---------------------------------------------------------------------------
// Launch
// ---------------------------------------------------------------------------
extern "C" void kernel_launch(void* const* d_in, const int* in_sizes, int n_in,
                              void* d_out, int out_size)
{
    const float* x      = (const float*)d_in[0];
    const float* W_qkv  = (const float*)d_in[1];
    const float* b_qkv  = (const float*)d_in[2];
    const float* W_proj = (const float*)d_in[3];
    const float* b_proj = (const float*)d_in[4];
    float* out = (float*)d_out;

    __nv_bfloat16 *xs, *as, *wqs, *wps;
    char *qsp, *ksp, *vsp;
    cudaGetSymbolAddress((void**)&xs,  g_xs);
    cudaGetSymbolAddress((void**)&as,  g_as);
    cudaGetSymbolAddress((void**)&wqs, g_wqs);
    cudaGetSymbolAddress((void**)&wps, g_wps);
    cudaGetSymbolAddress((void**)&qsp, g_qs);
    cudaGetSymbolAddress((void**)&ksp, g_ksp);
    cudaGetSymbolAddress((void**)&vsp, g_vsp);

    cudaFuncSetAttribute(gemm_bf16_kernel,
                         cudaFuncAttributeMaxDynamicSharedMemorySize, GEMM_SMEM);
    cudaFuncSetAttribute(flash_hmma_kernel,
                         cudaFuncAttributeMaxDynamicSharedMemorySize, FLASH_SMEM);

    // Splits: A operands [hi|hi|lo], B operands [hi|lo|hi]
    split_kernel<<<BT * CDIM / 8 / 256, 256>>>(x, xs, CDIM, 2 * CDIM);
    split_kernel<<<3 * CDIM * CDIM / 8 / 256, 256>>>(W_qkv, wqs, 2 * CDIM, CDIM);
    split_kernel<<<CDIM * CDIM / 8 / 256, 256>>>(W_proj, wps, 2 * CDIM, CDIM);

    // 1) QKV projection; epilogue writes split Q/K/V smem-image blocks directly
    gemm_bf16_kernel<<<dim3(3 * CDIM / 128, BT / 128), 256, GEMM_SMEM>>>(
        xs, wqs, b_qkv, nullptr, BT, 3 * CDIM, K3, qsp, ksp, vsp, 1);

    // 2) Causal flash attention (HMMA, split, all-cp.async); split output
    flash_hmma_kernel<<<dim3(TSEQ / 128, NH, BATCH), 256, FLASH_SMEM>>>(
        qsp, ksp, vsp, as);

    // 3) Output projection (fp32 + bias into d_out)
    gemm_bf16_kernel<<<dim3(CDIM / 128, BT / 128), 256, GEMM_SMEM>>>(
        as, wps, b_proj, out, BT, CDIM, K3, nullptr, nullptr, nullptr, 0);
}

// round 10
// speedup vs baseline: 1.3965x; 1.2542x over previous
#include <cuda_runtime.h>
#include <cuda_bf16.h>
#include <cuda_fp16.h>
#include <cstdint>
#include <math.h>

#define BATCH 4
#define TSEQ  2048
#define CDIM  1024
#define NH    16
#define HD    64
#define BT    (BATCH * TSEQ)
#define K2    (2 * CDIM)          // fp16 2-product extended K = 2048
#define NKT   (TSEQ / 64)         // 32 key tiles per (b,h)
#define NQT   (TSEQ / 128)        // 16 query tiles per (b,h)

// ---------------------------------------------------------------------------
// Scratch (__device__ globals; no allocation allowed)
// ---------------------------------------------------------------------------
__device__ __half g_xs[(size_t)BT * K2];             // x split  [hi|lo] fp16
__device__ __half g_as[(size_t)BT * K2];             // att split[hi|lo] fp16
__device__ __half g_wqs[(size_t)3 * CDIM * K2];      // W_qkv    [hi|hi] fp16
__device__ __half g_wps[(size_t)CDIM * K2];          // W_proj   [hi|hi] fp16
// Split Q: per (b,h,qt128) 32KB block = [hi 16KB | lo 16KB] bf16, smem-layout
__device__ char g_qs[(size_t)BATCH * NH * NQT * 32768];
// Split K/V: per (b,h,kt64) 16KB block = [hi 8KB | lo 8KB] bf16, smem-layout
__device__ char g_ksp[(size_t)BATCH * NH * NKT * 16384];
__device__ char g_vsp[(size_t)BATCH * NH * NKT * 16384];

// ---------------------------------------------------------------------------
// PTX helpers (sm_100-baseline safe: cp.async + ldmatrix + mma.sync only)
// ---------------------------------------------------------------------------
__device__ __forceinline__ uint32_t smem_u32(const void* p) {
    uint32_t a;
    asm("{ .reg .u64 t; cvta.to.shared.u64 t, %1; cvt.u32.u64 %0, t; }"
        : "=r"(a) : "l"(p));
    return a;
}

#define CPASYNC16(dst, src) \
    asm volatile("cp.async.cg.shared.global [%0], [%1], 16;" \
        :: "r"(dst), "l"(src))
#define CPASYNC_COMMIT() asm volatile("cp.async.commit_group;")
#define CPASYNC_WAIT1()  asm volatile("cp.async.wait_group 1;")
#define CPASYNC_WAIT2()  asm volatile("cp.async.wait_group 2;")

#define LDSM_X4(r, addr) \
    asm volatile("ldmatrix.sync.aligned.m8n8.x4.shared.b16 {%0,%1,%2,%3}, [%4];" \
        : "=r"((r)[0]), "=r"((r)[1]), "=r"((r)[2]), "=r"((r)[3]) : "r"(addr))

#define LDSM_X4_T(r, addr) \
    asm volatile("ldmatrix.sync.aligned.m8n8.x4.trans.shared.b16 {%0,%1,%2,%3}, [%4];" \
        : "=r"((r)[0]), "=r"((r)[1]), "=r"((r)[2]), "=r"((r)[3]) : "r"(addr))

#define MMA_BF16(d, a, br0, br1) \
    asm volatile("mma.sync.aligned.m16n8k16.row.col.f32.bf16.bf16.f32 " \
        "{%0,%1,%2,%3}, {%4,%5,%6,%7}, {%8,%9}, {%0,%1,%2,%3};" \
        : "+f"((d)[0]), "+f"((d)[1]), "+f"((d)[2]), "+f"((d)[3]) \
        : "r"((a)[0]), "r"((a)[1]), "r"((a)[2]), "r"((a)[3]), "r"(br0), "r"(br1))

#define MMA_F16(d, a, br0, br1) \
    asm volatile("mma.sync.aligned.m16n8k16.row.col.f32.f16.f16.f32 " \
        "{%0,%1,%2,%3}, {%4,%5,%6,%7}, {%8,%9}, {%0,%1,%2,%3};" \
        : "+f"((d)[0]), "+f"((d)[1]), "+f"((d)[2]), "+f"((d)[3]) \
        : "r"((a)[0]), "r"((a)[1]), "r"((a)[2]), "r"((a)[3]), "r"(br0), "r"(br1))

// pack two f32 -> bf16x2 (lo half = x0, hi half = x1)
#define PACK_BF16X2(res, x0, x1) \
    asm("cvt.rn.bf16x2.f32 %0, %1, %2;" : "=r"(res) : "f"(x1), "f"(x0))
// pack two f32 -> f16x2 (lo half = x0, hi half = x1)
#define PACK_F16X2(res, x0, x1) \
    asm("cvt.rn.f16x2.f32 %0, %1, %2;" : "=r"(res) : "f"(x1), "f"(x0))

// ---------------------------------------------------------------------------
// fp16 2-product split: fp32 [R,1024] -> fp16 [R,2048].
// dup=0 (A operand): [hi | lo]  where lo = x - fp16(x)
// dup=1 (B operand): [hi | hi]
// A'.B'^T = (Ahi+Alo).Bhi = A.Bhi ; error = A.(B-Bhi) ~ 2^-12 relative.
// ---------------------------------------------------------------------------
__global__ __launch_bounds__(256) void split16_kernel(
    const float* __restrict__ src, __half* __restrict__ dst, int dup)
{
    int idx = blockIdx.x * blockDim.x + threadIdx.x;
    int row = idx >> 7;
    int c8  = (idx & 127) << 3;

    const float* p = src + (size_t)row * CDIM + c8;
    float4 v0 = *(const float4*)p;
    float4 v1 = *(const float4*)(p + 4);
    float xs[8] = {v0.x, v0.y, v0.z, v0.w, v1.x, v1.y, v1.z, v1.w};

    uint32_t hv[4], lv[4];
    #pragma unroll
    for (int i = 0; i < 4; i++) {
        float x0 = xs[2*i], x1 = xs[2*i + 1];
        uint32_t hp; PACK_F16X2(hp, x0, x1);
        __half2 hh = *reinterpret_cast<__half2*>(&hp);
        float r0 = x0 - __low2float(hh);
        float r1 = x1 - __high2float(hh);
        uint32_t lp; PACK_F16X2(lp, r0, r1);
        hv[i] = hp; lv[i] = lp;
    }
    uint4 hq = make_uint4(hv[0], hv[1], hv[2], hv[3]);
    uint4 lq = make_uint4(lv[0], lv[1], lv[2], lv[3]);

    __half* base = dst + (size_t)row * K2;
    *reinterpret_cast<uint4*>(base + c8)        = hq;
    *reinterpret_cast<uint4*>(base + CDIM + c8) = dup ? hq : lq;
}

// ---------------------------------------------------------------------------
// fp16 NT GEMM via mma.sync (HMMA), 128x128 tile, 64x32 warp tile, 3-stage.
// mode 0: C = A.B^T + bias (fp32 store).
// mode 1 (QKV): epilogue splits outputs into bf16 hi/lo smem-image blocks:
//   Q (scaled 0.125) -> qs, K -> ksp, V -> vsp. No fp32 intermediate.
// ---------------------------------------------------------------------------
#define GSTAGE 32768           // A 16KB + B 16KB per stage
#define GEMM_SMEM (3 * GSTAGE) // 98304

__global__ __launch_bounds__(256) void gemm_f16_kernel(
    const __half* __restrict__ A, const __half* __restrict__ B,
    const float* __restrict__ bias, float* __restrict__ C,
    int M, int N, int K,
    char* __restrict__ qs, char* __restrict__ ksp, char* __restrict__ vsp,
    int mode)
{
    extern __shared__ char sm[];
    uint32_t smb = smem_u32(sm);
    const int tid  = threadIdx.x;
    const int lane = tid & 31;
    const int wid  = tid >> 5;
    const int wm   = wid >> 2;        // 0..1
    const int wn   = wid & 3;         // 0..3
    const int m0   = blockIdx.y * 128;
    const int n0   = blockIdx.x * 128;
    const int NK   = K >> 6;

    const size_t Kb = (size_t)K * 2;
    const char* Abase = (const char*)A + (size_t)m0 * Kb;
    const char* Bbase = (const char*)B + (size_t)n0 * Kb;

    const int lr = tid >> 3;
    const int lc = (tid & 7) << 4;

    float acc[4][4][4];
    #pragma unroll
    for (int i = 0; i < 4; i++)
        #pragma unroll
        for (int j = 0; j < 4; j++)
            #pragma unroll
            for (int r = 0; r < 4; r++) acc[i][j][r] = 0.f;

    const int lrow  = lane & 15;
    const int lhalf = (lane >> 4) << 4;
    uint32_t arow[4], axor[4], brow[2], bxor[2];
    #pragma unroll
    for (int mi = 0; mi < 4; mi++) {
        int r = wm * 64 + mi * 16 + lrow;
        arow[mi] = r * 128; axor[mi] = (r & 7) << 4;
    }
    #pragma unroll
    for (int bi = 0; bi < 2; bi++) {
        int r = wn * 32 + bi * 16 + lrow;
        brow[bi] = r * 128; bxor[bi] = (r & 7) << 4;
    }

    auto load_stage = [&](int kt, int s) {
        uint32_t sa = smb + s * GSTAGE;
        uint32_t sb = sa + 16384;
        size_t ktb = (size_t)kt << 7;
        #pragma unroll
        for (int p = 0; p < 4; p++) {
            int row = lr + p * 32;
            uint32_t so = row * 128 + (lc ^ ((row & 7) << 4));
            CPASYNC16(sa + so, Abase + (size_t)row * Kb + ktb + lc);
            CPASYNC16(sb + so, Bbase + (size_t)row * Kb + ktb + lc);
        }
    };

    load_stage(0, 0); CPASYNC_COMMIT();
    load_stage(1, 1); CPASYNC_COMMIT();
    load_stage(2, 2); CPASYNC_COMMIT();

    int slot = 0;
    for (int kt = 0; kt < NK; kt++) {
        CPASYNC_WAIT2();
        __syncthreads();
        uint32_t sa = smb + slot * GSTAGE;
        uint32_t sb = sa + 16384;

        #pragma unroll
        for (int ks = 0; ks < 4; ks++) {
            uint32_t kb = (ks << 5) + lhalf;
            uint32_t a[4][4], b[2][4];
            #pragma unroll
            for (int mi = 0; mi < 4; mi++)
                LDSM_X4(a[mi], sa + arow[mi] + (kb ^ axor[mi]));
            #pragma unroll
            for (int bi = 0; bi < 2; bi++)
                LDSM_X4(b[bi], sb + brow[bi] + (kb ^ bxor[bi]));
            #pragma unroll
            for (int mi = 0; mi < 4; mi++)
                #pragma unroll
                for (int ni = 0; ni < 4; ni++)
                    MMA_F16(acc[mi][ni], a[mi],
                            b[ni >> 1][ni & 1], b[ni >> 1][(ni & 1) + 2]);
        }
        __syncthreads();
        if (kt + 3 < NK) load_stage(kt + 3, slot);
        CPASYNC_COMMIT();
        slot = (slot == 2) ? 0 : slot + 1;
    }

    const int g  = lane >> 2;
    const int tg = (lane & 3) << 1;

    if (mode == 0) {
        #pragma unroll
        for (int mi = 0; mi < 4; mi++) {
            int r0 = m0 + wm * 64 + mi * 16 + g;
            #pragma unroll
            for (int ni = 0; ni < 4; ni++) {
                int col = n0 + wn * 32 + ni * 8 + tg;
                float b0 = bias[col], b1 = bias[col + 1];
                float2 v0 = {acc[mi][ni][0] + b0, acc[mi][ni][1] + b1};
                float2 v1 = {acc[mi][ni][2] + b0, acc[mi][ni][3] + b1};
                *(float2*)&C[(size_t)r0 * N + col] = v0;
                *(float2*)&C[(size_t)(r0 + 8) * N + col] = v1;
            }
        }
    } else {
        // QKV split epilogue (bf16 hi/lo). Region uniform per CTA.
        const int region = n0 >> 10;       // 0=Q, 1=K, 2=V
        const int ncol0  = n0 & 1023;
        #pragma unroll
        for (int mi = 0; mi < 4; mi++) {
            #pragma unroll
            for (int rr = 0; rr < 2; rr++) {
                int trow = m0 + wm * 64 + mi * 16 + g + rr * 8;
                int bb   = trow >> 11;          // batch
                int tloc = trow & 2047;         // token within batch
                #pragma unroll
                for (int ni = 0; ni < 4; ni++) {
                    int gcol = n0 + wn * 32 + ni * 8 + tg;
                    int colr = ncol0 + wn * 32 + ni * 8 + tg;
                    int h = colr >> 6;
                    int d = colr & 63;
                    float y0 = acc[mi][ni][rr * 2 + 0] + bias[gcol];
                    float y1 = acc[mi][ni][rr * 2 + 1] + bias[gcol + 1];
                    if (region == 0) { y0 *= 0.125f; y1 *= 0.125f; }
                    uint32_t hp; PACK_BF16X2(hp, y0, y1);
                    float h0 = __uint_as_float(hp << 16);
                    float h1 = __uint_as_float(hp & 0xffff0000u);
                    uint32_t lp; PACK_BF16X2(lp, y0 - h0, y1 - h1);
                    if (region == 0) {
                        char* blk = qs +
                            ((size_t)((bb * NH + h) * NQT + (tloc >> 7))) * 32768;
                        int rowb = tloc & 127;
                        uint32_t off = rowb * 128 +
                            (((uint32_t)(d * 2)) ^ ((rowb & 7) << 4));
                        *(uint32_t*)(blk + off)         = hp;
                        *(uint32_t*)(blk + 16384 + off) = lp;
                    } else {
                        char* blk = (region == 1 ? ksp : vsp) +
                            ((size_t)((bb * NH + h) * NKT + (tloc >> 6))) * 16384;
                        int rowb = tloc & 63;
                        uint32_t off = rowb * 128 +
                            (((uint32_t)(d * 2)) ^ ((rowb & 7) << 4));
                        *(uint32_t*)(blk + off)        = hp;
                        *(uint32_t*)(blk + 8192 + off) = lp;
                    }
                }
            }
        }
    }
}

// ---------------------------------------------------------------------------
// Flash attention via HMMA, bf16 hi/lo split (3-combo), causal.
// Q/K/V pre-split in GMEM smem-image blocks -> verbatim cp.async only.
// Epilogue writes attention output as fp16 [hi|lo] rows (g_as) for proj GEMM.
// ---------------------------------------------------------------------------
#define FSTG 32768
#define FLASH_SMEM (32768 + 2 * FSTG)   // 98304

__global__ __launch_bounds__(256, 1) void flash_hmma_kernel(
    const char* __restrict__ qs,
    const char* __restrict__ ksp, const char* __restrict__ vsp,
    __half* __restrict__ outs)
{
    extern __shared__ char sm[];
    uint32_t smb = smem_u32(sm);
    const uint32_t sQh = smb;
    const uint32_t sQl = smb + 16384;

    const int tid  = threadIdx.x;
    const int lane = tid & 31;
    const int w    = tid >> 5;
    const int g    = lane >> 2;
    const int t    = lane & 3;
    const int qt   = (gridDim.x - 1) - blockIdx.x;   // heavy tiles first
    const int h    = blockIdx.y;
    const int b    = blockIdx.z;
    const int q0   = qt * 128;

    const char* qblk = qs + ((size_t)((b * NH + h) * NQT + qt)) * 32768;
    const char* kbh = ksp + ((size_t)((b * NH + h) * NKT)) * 16384;
    const char* vbh = vsp + ((size_t)((b * NH + h) * NKT)) * 16384;

    const int nkt = 2 * qt + 2;

    auto load_stage = [&](int kt2, int s) {
        uint32_t d = smb + 32768 + s * FSTG;
        const char* sk = kbh + (size_t)kt2 * 16384;
        const char* sv = vbh + (size_t)kt2 * 16384;
        #pragma unroll
        for (int i = 0; i < 4; i++) {
            uint32_t o = (uint32_t)(tid + i * 256) * 16;
            CPASYNC16(d + o, sk + o);
            CPASYNC16(d + 16384 + o, sv + o);
        }
    };

    // Q (32KB verbatim) + stage 0 in commit-group 0
    #pragma unroll
    for (int i = 0; i < 8; i++) {
        uint32_t o = (uint32_t)(tid + i * 256) * 16;
        CPASYNC16(smb + o, qblk + o);
    }
    load_stage(0, 0); CPASYNC_COMMIT();
    if (nkt > 1) load_stage(1, 1);
    CPASYNC_COMMIT();

    const int lrow  = lane & 15;
    const int lhalf = (lane >> 4) << 4;
    const uint32_t aoff = (uint32_t)((w * 16 + lrow) * 128);
    const uint32_t axor = (uint32_t)((lrow & 7) << 4);
    const uint32_t kxor = axor;

    float o[8][4];
    #pragma unroll
    for (int i = 0; i < 8; i++)
        #pragma unroll
        for (int j = 0; j < 4; j++) o[i][j] = 0.f;
    float m0 = -1e30f, m1 = -1e30f, l0 = 0.f, l1 = 0.f;
    const int qw = q0 + w * 16;

    for (int kt = 0; kt < nkt; kt++) {
        const int k0 = kt * 64;
        CPASYNC_WAIT1();
        __syncthreads();
        const uint32_t sKh = smb + 32768 + (kt & 1) * FSTG;
        const uint32_t sKl = sKh + 8192;
        const uint32_t sVh = sKh + 16384;
        const uint32_t sVl = sKh + 24576;

        float s[8][4];
        #pragma unroll
        for (int i = 0; i < 8; i++)
            #pragma unroll
            for (int j = 0; j < 4; j++) s[i][j] = 0.f;

        #pragma unroll
        for (int kc = 0; kc < 4; kc++) {
            uint32_t colb = (uint32_t)(kc * 32 + lhalf);
            uint32_t ah[4], al[4];
            LDSM_X4(ah, sQh + aoff + (colb ^ axor));
            LDSM_X4(al, sQl + aoff + (colb ^ axor));
            #pragma unroll
            for (int gk = 0; gk < 4; gk++) {
                uint32_t ro = (uint32_t)((gk * 16 + lrow) * 128);
                uint32_t kh[4], kl[4];
                LDSM_X4(kh, sKh + ro + (colb ^ kxor));
                LDSM_X4(kl, sKl + ro + (colb ^ kxor));
                #pragma unroll
                for (int pp = 0; pp < 2; pp++) {
                    int nt = gk * 2 + pp;
                    MMA_BF16(s[nt], ah, kh[pp], kh[pp + 2]);
                    MMA_BF16(s[nt], ah, kl[pp], kl[pp + 2]);
                    MMA_BF16(s[nt], al, kh[pp], kh[pp + 2]);
                }
            }
        }

        if (k0 + 63 > qw) {
            int r0 = qw + g, r1 = qw + g + 8;
            #pragma unroll
            for (int nt = 0; nt < 8; nt++) {
                int col = k0 + nt * 8 + 2 * t;
                if (col     > r0) s[nt][0] = -1e30f;
                if (col + 1 > r0) s[nt][1] = -1e30f;
                if (col     > r1) s[nt][2] = -1e30f;
                if (col + 1 > r1) s[nt][3] = -1e30f;
            }
        }

        float mx0 = -1e30f, mx1 = -1e30f;
        #pragma unroll
        for (int nt = 0; nt < 8; nt++) {
            mx0 = fmaxf(mx0, fmaxf(s[nt][0], s[nt][1]));
            mx1 = fmaxf(mx1, fmaxf(s[nt][2], s[nt][3]));
        }
        mx0 = fmaxf(mx0, __shfl_xor_sync(0xffffffffu, mx0, 1));
        mx0 = fmaxf(mx0, __shfl_xor_sync(0xffffffffu, mx0, 2));
        mx1 = fmaxf(mx1, __shfl_xor_sync(0xffffffffu, mx1, 1));
        mx1 = fmaxf(mx1, __shfl_xor_sync(0xffffffffu, mx1, 2));
        float mn0 = fmaxf(m0, mx0), mn1 = fmaxf(m1, mx1);
        float c0 = __expf(m0 - mn0), c1 = __expf(m1 - mn1);
        float sum0 = 0.f, sum1 = 0.f;
        #pragma unroll
        for (int nt = 0; nt < 8; nt++) {
            s[nt][0] = __expf(s[nt][0] - mn0);
            s[nt][1] = __expf(s[nt][1] - mn0);
            s[nt][2] = __expf(s[nt][2] - mn1);
            s[nt][3] = __expf(s[nt][3] - mn1);
            sum0 += s[nt][0] + s[nt][1];
            sum1 += s[nt][2] + s[nt][3];
        }
        sum0 += __shfl_xor_sync(0xffffffffu, sum0, 1);
        sum0 += __shfl_xor_sync(0xffffffffu, sum0, 2);
        sum1 += __shfl_xor_sync(0xffffffffu, sum1, 1);
        sum1 += __shfl_xor_sync(0xffffffffu, sum1, 2);
        l0 = l0 * c0 + sum0; l1 = l1 * c1 + sum1;
        m0 = mn0; m1 = mn1;
        #pragma unroll
        for (int nt = 0; nt < 8; nt++) {
            o[nt][0] *= c0; o[nt][1] *= c0;
            o[nt][2] *= c1; o[nt][3] *= c1;
        }

        uint32_t ph[16], pl[16];
        #pragma unroll
        for (int c2 = 0; c2 < 8; c2++) {
            int ib = (c2 >> 1) * 4 + (c2 & 1) * 2;
            uint32_t p01, p23;
            PACK_BF16X2(p01, s[c2][0], s[c2][1]);
            PACK_BF16X2(p23, s[c2][2], s[c2][3]);
            float h0 = __uint_as_float(p01 << 16);
            float h1 = __uint_as_float(p01 & 0xffff0000u);
            float h2 = __uint_as_float(p23 << 16);
            float h3 = __uint_as_float(p23 & 0xffff0000u);
            uint32_t q01, q23;
            PACK_BF16X2(q01, s[c2][0] - h0, s[c2][1] - h1);
            PACK_BF16X2(q23, s[c2][2] - h2, s[c2][3] - h3);
            ph[ib] = p01; ph[ib + 1] = p23;
            pl[ib] = q01; pl[ib + 1] = q23;
        }

        #pragma unroll
        for (int kc = 0; kc < 4; kc++) {
            const uint32_t* aH = &ph[kc * 4];
            const uint32_t* aL = &pl[kc * 4];
            uint32_t ro = (uint32_t)((kc * 16 + lrow) * 128);
            #pragma unroll
            for (int j = 0; j < 4; j++) {
                uint32_t cb = ((uint32_t)(j * 32 + lhalf)) ^ kxor;
                uint32_t vh[4], vl[4];
                LDSM_X4_T(vh, sVh + ro + cb);
                LDSM_X4_T(vl, sVl + ro + cb);
                MMA_BF16(o[2*j],     aH, vh[0], vh[1]);
                MMA_BF16(o[2*j + 1], aH, vh[2], vh[3]);
                MMA_BF16(o[2*j],     aH, vl[0], vl[1]);
                MMA_BF16(o[2*j + 1], aH, vl[2], vl[3]);
                MMA_BF16(o[2*j],     aL, vh[0], vh[1]);
                MMA_BF16(o[2*j + 1], aL, vh[2], vh[3]);
            }
        }

        __syncthreads();
        if (kt + 2 < nkt) load_stage(kt + 2, kt & 1);
        CPASYNC_COMMIT();
    }

    // ---- finalize: O /= l, write fp16 [hi|lo] rows of g_as ----
    float inv0 = 1.0f / l0, inv1 = 1.0f / l1;
    int r0 = qw + g, r1 = qw + g + 8;
    __half* ab = outs + (size_t)(b * TSEQ) * K2 + h * 64;
    uint32_t* p0 = (uint32_t*)(ab + (size_t)r0 * K2);
    uint32_t* p1 = (uint32_t*)(ab + (size_t)r1 * K2);
    #pragma unroll
    for (int nt = 0; nt < 8; nt++) {
        int c2 = (nt * 8 + 2 * t) >> 1;      // uint32 index within row
        float y00 = o[nt][0] * inv0, y01 = o[nt][1] * inv0;
        float y10 = o[nt][2] * inv1, y11 = o[nt][3] * inv1;
        uint32_t h0p, h1p;
        PACK_F16X2(h0p, y00, y01);
        PACK_F16X2(h1p, y10, y11);
        __half2 hh0 = *reinterpret_cast<__half2*>(&h0p);
        __half2 hh1 = *reinterpret_cast<__half2*>(&h1p);
        uint32_t l0p, l1p;
        PACK_F16X2(l0p, y00 - __low2float(hh0), y01 - __high2float(hh0));
        PACK_F16X2(l1p, y10 - __low2float(hh1), y11 - __high2float(hh1));
        p0[c2] = h0p; p0[c2 + 512] = l0p;
        p1[c2] = h1p; p1[c2 + 512] = l1p;
    }
}

// ---------------------------------------------------------------------------
// Launch
// ---------------------------------------------------------------------------
extern "C" void kernel_launch(void* const* d_in, const int* in_sizes, int n_in,
                              void* d_out, int out_size)
{
    const float* x      = (const float*)d_in[0];
    const float* W_qkv  = (const float*)d_in[1];
    const float* b_qkv  = (const float*)d_in[2];
    const float* W_proj = (const float*)d_in[3];
    const float* b_proj = (const float*)d_in[4];
    float* out = (float*)d_out;

    __half *xs, *as, *wqs, *wps;
    char *qsp, *ksp, *vsp;
    cudaGetSymbolAddress((void**)&xs,  g_xs);
    cudaGetSymbolAddress((void**)&as,  g_as);
    cudaGetSymbolAddress((void**)&wqs, g_wqs);
    cudaGetSymbolAddress((void**)&wps, g_wps);
    cudaGetSymbolAddress((void**)&qsp, g_qs);
    cudaGetSymbolAddress((void**)&ksp, g_ksp);
    cudaGetSymbolAddress((void**)&vsp, g_vsp);

    cudaFuncSetAttribute(gemm_f16_kernel,
                         cudaFuncAttributeMaxDynamicSharedMemorySize, GEMM_SMEM);
    cudaFuncSetAttribute(flash_hmma_kernel,
                         cudaFuncAttributeMaxDynamicSharedMemorySize, FLASH_SMEM);

    // fp16 2-product splits: A operands [hi|lo], B operands [hi|hi]
    split16_kernel<<<BT * CDIM / 8 / 256, 256>>>(x, xs, 0);
    split16_kernel<<<3 * CDIM * CDIM / 8 / 256, 256>>>(W_qkv, wqs, 1);
    split16_kernel<<<CDIM * CDIM / 8 / 256, 256>>>(W_proj, wps, 1);

    // 1) QKV projection (fp16 2-product); epilogue writes split Q/K/V blocks
    gemm_f16_kernel<<<dim3(3 * CDIM / 128, BT / 128), 256, GEMM_SMEM>>>(
        xs, wqs, b_qkv, nullptr, BT, 3 * CDIM, K2, qsp, ksp, vsp, 1);

    // 2) Causal flash attention (bf16 3-combo HMMA); fp16 [hi|lo] output
    flash_hmma_kernel<<<dim3(TSEQ / 128, NH, BATCH), 256, FLASH_SMEM>>>(
        qsp, ksp, vsp, as);

    // 3) Output projection (fp16 2-product, fp32 + bias into d_out)
    gemm_f16_kernel<<<dim3(CDIM / 128, BT / 128), 256, GEMM_SMEM>>>(
        as, wps, b_proj, out, BT, CDIM, K2, nullptr, nullptr, nullptr, 0);
}

// round 13
// speedup vs baseline: 1.5739x; 1.1270x over previous
#include <cuda_runtime.h>
#include <cuda_bf16.h>
#include <cuda_fp16.h>
#include <cstdint>
#include <math.h>

#define BATCH 4
#define TSEQ  2048
#define CDIM  1024
#define NH    16
#define HD    64
#define BT    (BATCH * TSEQ)
#define K2    (2 * CDIM)          // fp16 2-product extended K = 2048
#define NKT   (TSEQ / 64)         // 32 key tiles per (b,h)
#define NQT   (TSEQ / 128)        // 16 query tiles per (b,h)

// ---------------------------------------------------------------------------
// Scratch (__device__ globals; no allocation allowed)
// ---------------------------------------------------------------------------
__device__ __half g_xs[(size_t)BT * K2];             // x split  [hi|lo] fp16
__device__ __half g_as[(size_t)BT * K2];             // att split[hi|lo] fp16
__device__ __half g_wqs[(size_t)3 * CDIM * K2];      // W_qkv    [hi|hi] fp16
__device__ __half g_wps[(size_t)CDIM * K2];          // W_proj   [hi|hi] fp16
// Split Q: per (b,h,qt128) 32KB block = [hi 16KB | lo 16KB] fp16, smem-layout
__device__ char g_qs[(size_t)BATCH * NH * NQT * 32768];
// K: per (b,h,kt64) 8KB block, single fp16, smem-layout
__device__ char g_ksp[(size_t)BATCH * NH * NKT * 8192];
// V: per (b,h,kt64) 16KB block = [hi 8KB | lo 8KB] fp16, smem-layout
__device__ char g_vsp[(size_t)BATCH * NH * NKT * 16384];

// ---------------------------------------------------------------------------
// PTX helpers (sm_100-baseline safe: cp.async + ldmatrix + mma.sync only)
// ---------------------------------------------------------------------------
__device__ __forceinline__ uint32_t smem_u32(const void* p) {
    uint32_t a;
    asm("{ .reg .u64 t; cvta.to.shared.u64 t, %1; cvt.u32.u64 %0, t; }"
        : "=r"(a) : "l"(p));
    return a;
}

#define CPASYNC16(dst, src) \
    asm volatile("cp.async.cg.shared.global [%0], [%1], 16;" \
        :: "r"(dst), "l"(src))
#define CPASYNC_COMMIT() asm volatile("cp.async.commit_group;")
#define CPASYNC_WAIT1()  asm volatile("cp.async.wait_group 1;")
#define CPASYNC_WAIT2()  asm volatile("cp.async.wait_group 2;")

#define LDSM_X4(r, addr) \
    asm volatile("ldmatrix.sync.aligned.m8n8.x4.shared.b16 {%0,%1,%2,%3}, [%4];" \
        : "=r"((r)[0]), "=r"((r)[1]), "=r"((r)[2]), "=r"((r)[3]) : "r"(addr))

#define LDSM_X4_T(r, addr) \
    asm volatile("ldmatrix.sync.aligned.m8n8.x4.trans.shared.b16 {%0,%1,%2,%3}, [%4];" \
        : "=r"((r)[0]), "=r"((r)[1]), "=r"((r)[2]), "=r"((r)[3]) : "r"(addr))

#define MMA_F16(d, a, br0, br1) \
    asm volatile("mma.sync.aligned.m16n8k16.row.col.f32.f16.f16.f32 " \
        "{%0,%1,%2,%3}, {%4,%5,%6,%7}, {%8,%9}, {%0,%1,%2,%3};" \
        : "+f"((d)[0]), "+f"((d)[1]), "+f"((d)[2]), "+f"((d)[3]) \
        : "r"((a)[0]), "r"((a)[1]), "r"((a)[2]), "r"((a)[3]), "r"(br0), "r"(br1))

// pack two f32 -> f16x2 (lo half = x0, hi half = x1)
#define PACK_F16X2(res, x0, x1) \
    asm("cvt.rn.f16x2.f32 %0, %1, %2;" : "=r"(res) : "f"(x1), "f"(x0))

// ---------------------------------------------------------------------------
// fp16 2-product split: fp32 [R,1024] -> fp16 [R,2048].
// dup=0 (A operand): [hi | lo]  where lo = x - fp16(x)
// dup=1 (B operand): [hi | hi]
// A'.B'^T = (Ahi+Alo).Bhi = A.Bhi ; error = A.(B-Bhi) ~ 2^-12 relative.
// ---------------------------------------------------------------------------
__global__ __launch_bounds__(256) void split16_kernel(
    const float* __restrict__ src, __half* __restrict__ dst, int dup)
{
    int idx = blockIdx.x * blockDim.x + threadIdx.x;
    int row = idx >> 7;
    int c8  = (idx & 127) << 3;

    const float* p = src + (size_t)row * CDIM + c8;
    float4 v0 = *(const float4*)p;
    float4 v1 = *(const float4*)(p + 4);
    float xs[8] = {v0.x, v0.y, v0.z, v0.w, v1.x, v1.y, v1.z, v1.w};

    uint32_t hv[4], lv[4];
    #pragma unroll
    for (int i = 0; i < 4; i++) {
        float x0 = xs[2*i], x1 = xs[2*i + 1];
        uint32_t hp; PACK_F16X2(hp, x0, x1);
        __half2 hh = *reinterpret_cast<__half2*>(&hp);
        float r0 = x0 - __low2float(hh);
        float r1 = x1 - __high2float(hh);
        uint32_t lp; PACK_F16X2(lp, r0, r1);
        hv[i] = hp; lv[i] = lp;
    }
    uint4 hq = make_uint4(hv[0], hv[1], hv[2], hv[3]);
    uint4 lq = make_uint4(lv[0], lv[1], lv[2], lv[3]);

    __half* base = dst + (size_t)row * K2;
    *reinterpret_cast<uint4*>(base + c8)        = hq;
    *reinterpret_cast<uint4*>(base + CDIM + c8) = dup ? hq : lq;
}

// ---------------------------------------------------------------------------
// fp16 NT GEMM via mma.sync (HMMA), 128x128 tile, 64x32 warp tile, 3-stage.
// mode 0: C = A.B^T + bias (fp32 store).
// mode 1 (QKV): epilogue writes fp16 smem-image blocks:
//   Q (scaled 0.125) hi/lo -> qs ; K single -> ksp ; V hi/lo -> vsp.
// ---------------------------------------------------------------------------
#define GSTAGE 32768           // A 16KB + B 16KB per stage
#define GEMM_SMEM (3 * GSTAGE) // 98304

__global__ __launch_bounds__(256) void gemm_f16_kernel(
    const __half* __restrict__ A, const __half* __restrict__ B,
    const float* __restrict__ bias, float* __restrict__ C,
    int M, int N, int K,
    char* __restrict__ qs, char* __restrict__ ksp, char* __restrict__ vsp,
    int mode)
{
    extern __shared__ char sm[];
    uint32_t smb = smem_u32(sm);
    const int tid  = threadIdx.x;
    const int lane = tid & 31;
    const int wid  = tid >> 5;
    const int wm   = wid >> 2;        // 0..1
    const int wn   = wid & 3;         // 0..3
    const int m0   = blockIdx.y * 128;
    const int n0   = blockIdx.x * 128;
    const int NK   = K >> 6;

    const size_t Kb = (size_t)K * 2;
    const char* Abase = (const char*)A + (size_t)m0 * Kb;
    const char* Bbase = (const char*)B + (size_t)n0 * Kb;

    const int lr = tid >> 3;
    const int lc = (tid & 7) << 4;

    float acc[4][4][4];
    #pragma unroll
    for (int i = 0; i < 4; i++)
        #pragma unroll
        for (int j = 0; j < 4; j++)
            #pragma unroll
            for (int r = 0; r < 4; r++) acc[i][j][r] = 0.f;

    const int lrow  = lane & 15;
    const int lhalf = (lane >> 4) << 4;
    uint32_t arow[4], axor[4], brow[2], bxor[2];
    #pragma unroll
    for (int mi = 0; mi < 4; mi++) {
        int r = wm * 64 + mi * 16 + lrow;
        arow[mi] = r * 128; axor[mi] = (r & 7) << 4;
    }
    #pragma unroll
    for (int bi = 0; bi < 2; bi++) {
        int r = wn * 32 + bi * 16 + lrow;
        brow[bi] = r * 128; bxor[bi] = (r & 7) << 4;
    }

    auto load_stage = [&](int kt, int s) {
        uint32_t sa = smb + s * GSTAGE;
        uint32_t sb = sa + 16384;
        size_t ktb = (size_t)kt << 7;
        #pragma unroll
        for (int p = 0; p < 4; p++) {
            int row = lr + p * 32;
            uint32_t so = row * 128 + (lc ^ ((row & 7) << 4));
            CPASYNC16(sa + so, Abase + (size_t)row * Kb + ktb + lc);
            CPASYNC16(sb + so, Bbase + (size_t)row * Kb + ktb + lc);
        }
    };

    load_stage(0, 0); CPASYNC_COMMIT();
    load_stage(1, 1); CPASYNC_COMMIT();
    load_stage(2, 2); CPASYNC_COMMIT();

    int slot = 0;
    for (int kt = 0; kt < NK; kt++) {
        CPASYNC_WAIT2();
        __syncthreads();
        uint32_t sa = smb + slot * GSTAGE;
        uint32_t sb = sa + 16384;

        #pragma unroll
        for (int ks = 0; ks < 4; ks++) {
            uint32_t kb = (ks << 5) + lhalf;
            uint32_t a[4][4], b[2][4];
            #pragma unroll
            for (int mi = 0; mi < 4; mi++)
                LDSM_X4(a[mi], sa + arow[mi] + (kb ^ axor[mi]));
            #pragma unroll
            for (int bi = 0; bi < 2; bi++)
                LDSM_X4(b[bi], sb + brow[bi] + (kb ^ bxor[bi]));
            #pragma unroll
            for (int mi = 0; mi < 4; mi++)
                #pragma unroll
                for (int ni = 0; ni < 4; ni++)
                    MMA_F16(acc[mi][ni], a[mi],
                            b[ni >> 1][ni & 1], b[ni >> 1][(ni & 1) + 2]);
        }
        __syncthreads();
        if (kt + 3 < NK) load_stage(kt + 3, slot);
        CPASYNC_COMMIT();
        slot = (slot == 2) ? 0 : slot + 1;
    }

    const int g  = lane >> 2;
    const int tg = (lane & 3) << 1;

    if (mode == 0) {
        #pragma unroll
        for (int mi = 0; mi < 4; mi++) {
            int r0 = m0 + wm * 64 + mi * 16 + g;
            #pragma unroll
            for (int ni = 0; ni < 4; ni++) {
                int col = n0 + wn * 32 + ni * 8 + tg;
                float b0 = bias[col], b1 = bias[col + 1];
                float2 v0 = {acc[mi][ni][0] + b0, acc[mi][ni][1] + b1};
                float2 v1 = {acc[mi][ni][2] + b0, acc[mi][ni][3] + b1};
                *(float2*)&C[(size_t)r0 * N + col] = v0;
                *(float2*)&C[(size_t)(r0 + 8) * N + col] = v1;
            }
        }
    } else {
        // QKV fp16 split epilogue. Region uniform per CTA.
        const int region = n0 >> 10;       // 0=Q, 1=K, 2=V
        const int ncol0  = n0 & 1023;
        #pragma unroll
        for (int mi = 0; mi < 4; mi++) {
            #pragma unroll
            for (int rr = 0; rr < 2; rr++) {
                int trow = m0 + wm * 64 + mi * 16 + g + rr * 8;
                int bb   = trow >> 11;          // batch
                int tloc = trow & 2047;         // token within batch
                #pragma unroll
                for (int ni = 0; ni < 4; ni++) {
                    int gcol = n0 + wn * 32 + ni * 8 + tg;
                    int colr = ncol0 + wn * 32 + ni * 8 + tg;
                    int h = colr >> 6;
                    int d = colr & 63;
                    float y0 = acc[mi][ni][rr * 2 + 0] + bias[gcol];
                    float y1 = acc[mi][ni][rr * 2 + 1] + bias[gcol + 1];
                    if (region == 0) { y0 *= 0.125f; y1 *= 0.125f; }
                    uint32_t hp; PACK_F16X2(hp, y0, y1);
                    if (region == 1) {
                        char* blk = ksp +
                            ((size_t)((bb * NH + h) * NKT + (tloc >> 6))) * 8192;
                        int rowb = tloc & 63;
                        uint32_t off = rowb * 128 +
                            (((uint32_t)(d * 2)) ^ ((rowb & 7) << 4));
                        *(uint32_t*)(blk + off) = hp;
                    } else {
                        __half2 hh = *reinterpret_cast<__half2*>(&hp);
                        uint32_t lp;
                        PACK_F16X2(lp, y0 - __low2float(hh), y1 - __high2float(hh));
                        if (region == 0) {
                            char* blk = qs +
                                ((size_t)((bb * NH + h) * NQT + (tloc >> 7))) * 32768;
                            int rowb = tloc & 127;
                            uint32_t off = rowb * 128 +
                                (((uint32_t)(d * 2)) ^ ((rowb & 7) << 4));
                            *(uint32_t*)(blk + off)         = hp;
                            *(uint32_t*)(blk + 16384 + off) = lp;
                        } else {
                            char* blk = vsp +
                                ((size_t)((bb * NH + h) * NKT + (tloc >> 6))) * 16384;
                            int rowb = tloc & 63;
                            uint32_t off = rowb * 128 +
                                (((uint32_t)(d * 2)) ^ ((rowb & 7) << 4));
                            *(uint32_t*)(blk + off)        = hp;
                            *(uint32_t*)(blk + 8192 + off) = lp;
                        }
                    }
                }
            }
        }
    }
}

// ---------------------------------------------------------------------------
// Flash attention via fp16 HMMA, causal.
// S = (Qhi+Qlo).K   (Q exact to 2^-22, K single fp16)   -> 2 combos
// O += P.(Vhi+Vlo)  (P single fp16, V exact to 2^-22)   -> 2 combos
// Q/K/V pre-split fp16 smem-image blocks -> verbatim cp.async only.
// Epilogue writes attention output as fp16 [hi|lo] rows (g_as).
// smem: Q 32KB + 2 stages x [K 8KB | Vh 8KB | Vl 8KB] = 80KB.
// ---------------------------------------------------------------------------
#define FSTG 24576
#define FLASH_SMEM (32768 + 2 * FSTG)   // 81920

__global__ __launch_bounds__(256, 1) void flash_hmma_kernel(
    const char* __restrict__ qs,
    const char* __restrict__ ksp, const char* __restrict__ vsp,
    __half* __restrict__ outs)
{
    extern __shared__ char sm[];
    uint32_t smb = smem_u32(sm);
    const uint32_t sQh = smb;
    const uint32_t sQl = smb + 16384;

    const int tid  = threadIdx.x;
    const int lane = tid & 31;
    const int w    = tid >> 5;
    const int g    = lane >> 2;
    const int t    = lane & 3;
    const int qt   = (gridDim.x - 1) - blockIdx.x;   // heavy tiles first
    const int h    = blockIdx.y;
    const int b    = blockIdx.z;
    const int q0   = qt * 128;

    const char* qblk = qs + ((size_t)((b * NH + h) * NQT + qt)) * 32768;
    const char* kbh = ksp + ((size_t)((b * NH + h) * NKT)) * 8192;
    const char* vbh = vsp + ((size_t)((b * NH + h) * NKT)) * 16384;

    const int nkt = 2 * qt + 2;

    // stage = [K 8KB | Vh 8KB | Vl 8KB]; 1536 16B units / 256 thr = 6 each
    auto load_stage = [&](int kt2, int s) {
        uint32_t d = smb + 32768 + s * FSTG;
        const char* sk = kbh + (size_t)kt2 * 8192;
        const char* sv = vbh + (size_t)kt2 * 16384;
        #pragma unroll
        for (int i = 0; i < 2; i++) {
            uint32_t o = (uint32_t)(tid + i * 256) * 16;
            CPASYNC16(d + o, sk + o);
        }
        #pragma unroll
        for (int i = 0; i < 4; i++) {
            uint32_t o = (uint32_t)(tid + i * 256) * 16;
            CPASYNC16(d + 8192 + o, sv + o);
        }
    };

    // Q (32KB verbatim) + stage 0 in commit-group 0
    #pragma unroll
    for (int i = 0; i < 8; i++) {
        uint32_t o = (uint32_t)(tid + i * 256) * 16;
        CPASYNC16(smb + o, qblk + o);
    }
    load_stage(0, 0); CPASYNC_COMMIT();
    if (nkt > 1) load_stage(1, 1);
    CPASYNC_COMMIT();

    const int lrow  = lane & 15;
    const int lhalf = (lane >> 4) << 4;
    const uint32_t aoff = (uint32_t)((w * 16 + lrow) * 128);
    const uint32_t axor = (uint32_t)((lrow & 7) << 4);
    const uint32_t kxor = axor;

    float o[8][4];
    #pragma unroll
    for (int i = 0; i < 8; i++)
        #pragma unroll
        for (int j = 0; j < 4; j++) o[i][j] = 0.f;
    float m0 = -1e30f, m1 = -1e30f, l0 = 0.f, l1 = 0.f;
    const int qw = q0 + w * 16;

    for (int kt = 0; kt < nkt; kt++) {
        const int k0 = kt * 64;
        CPASYNC_WAIT1();
        __syncthreads();
        const uint32_t sK  = smb + 32768 + (kt & 1) * FSTG;
        const uint32_t sVh = sK + 8192;
        const uint32_t sVl = sK + 16384;

        // ---- S = Q.K^T (2 combos), warp tile 16 x 64 ----
        float s[8][4];
        #pragma unroll
        for (int i = 0; i < 8; i++)
            #pragma unroll
            for (int j = 0; j < 4; j++) s[i][j] = 0.f;

        #pragma unroll
        for (int kc = 0; kc < 4; kc++) {
            uint32_t colb = (uint32_t)(kc * 32 + lhalf);
            uint32_t ah[4], al[4];
            LDSM_X4(ah, sQh + aoff + (colb ^ axor));
            LDSM_X4(al, sQl + aoff + (colb ^ axor));
            #pragma unroll
            for (int gk = 0; gk < 4; gk++) {
                uint32_t ro = (uint32_t)((gk * 16 + lrow) * 128);
                uint32_t kh[4];
                LDSM_X4(kh, sK + ro + (colb ^ kxor));
                #pragma unroll
                for (int pp = 0; pp < 2; pp++) {
                    int nt = gk * 2 + pp;
                    MMA_F16(s[nt], ah, kh[pp], kh[pp + 2]);
                    MMA_F16(s[nt], al, kh[pp], kh[pp + 2]);
                }
            }
        }

        if (k0 + 63 > qw) {
            int r0 = qw + g, r1 = qw + g + 8;
            #pragma unroll
            for (int nt = 0; nt < 8; nt++) {
                int col = k0 + nt * 8 + 2 * t;
                if (col     > r0) s[nt][0] = -1e30f;
                if (col + 1 > r0) s[nt][1] = -1e30f;
                if (col     > r1) s[nt][2] = -1e30f;
                if (col + 1 > r1) s[nt][3] = -1e30f;
            }
        }

        float mx0 = -1e30f, mx1 = -1e30f;
        #pragma unroll
        for (int nt = 0; nt < 8; nt++) {
            mx0 = fmaxf(mx0, fmaxf(s[nt][0], s[nt][1]));
            mx1 = fmaxf(mx1, fmaxf(s[nt][2], s[nt][3]));
        }
        mx0 = fmaxf(mx0, __shfl_xor_sync(0xffffffffu, mx0, 1));
        mx0 = fmaxf(mx0, __shfl_xor_sync(0xffffffffu, mx0, 2));
        mx1 = fmaxf(mx1, __shfl_xor_sync(0xffffffffu, mx1, 1));
        mx1 = fmaxf(mx1, __shfl_xor_sync(0xffffffffu, mx1, 2));
        float mn0 = fmaxf(m0, mx0), mn1 = fmaxf(m1, mx1);
        float c0 = __expf(m0 - mn0), c1 = __expf(m1 - mn1);
        float sum0 = 0.f, sum1 = 0.f;
        #pragma unroll
        for (int nt = 0; nt < 8; nt++) {
            s[nt][0] = __expf(s[nt][0] - mn0);
            s[nt][1] = __expf(s[nt][1] - mn0);
            s[nt][2] = __expf(s[nt][2] - mn1);
            s[nt][3] = __expf(s[nt][3] - mn1);
            sum0 += s[nt][0] + s[nt][1];
            sum1 += s[nt][2] + s[nt][3];
        }
        sum0 += __shfl_xor_sync(0xffffffffu, sum0, 1);
        sum0 += __shfl_xor_sync(0xffffffffu, sum0, 2);
        sum1 += __shfl_xor_sync(0xffffffffu, sum1, 1);
        sum1 += __shfl_xor_sync(0xffffffffu, sum1, 2);
        l0 = l0 * c0 + sum0; l1 = l1 * c1 + sum1;
        m0 = mn0; m1 = mn1;
        #pragma unroll
        for (int nt = 0; nt < 8; nt++) {
            o[nt][0] *= c0; o[nt][1] *= c0;
            o[nt][2] *= c1; o[nt][3] *= c1;
        }

        // ---- pack P (single fp16) into A-fragments, direct from S regs ----
        uint32_t ph[16];
        #pragma unroll
        for (int c2 = 0; c2 < 8; c2++) {
            int ib = (c2 >> 1) * 4 + (c2 & 1) * 2;
            uint32_t p01, p23;
            PACK_F16X2(p01, s[c2][0], s[c2][1]);
            PACK_F16X2(p23, s[c2][2], s[c2][3]);
            ph[ib] = p01; ph[ib + 1] = p23;
        }

        // ---- O += P.(Vhi+Vlo) (2 combos), contraction over 64 keys ----
        #pragma unroll
        for (int kc = 0; kc < 4; kc++) {
            const uint32_t* aH = &ph[kc * 4];
            uint32_t ro = (uint32_t)((kc * 16 + lrow) * 128);
            #pragma unroll
            for (int j = 0; j < 4; j++) {
                uint32_t cb = ((uint32_t)(j * 32 + lhalf)) ^ kxor;
                uint32_t vh[4], vl[4];
                LDSM_X4_T(vh, sVh + ro + cb);
                LDSM_X4_T(vl, sVl + ro + cb);
                MMA_F16(o[2*j],     aH, vh[0], vh[1]);
                MMA_F16(o[2*j + 1], aH, vh[2], vh[3]);
                MMA_F16(o[2*j],     aH, vl[0], vl[1]);
                MMA_F16(o[2*j + 1], aH, vl[2], vl[3]);
            }
        }

        __syncthreads();
        if (kt + 2 < nkt) load_stage(kt + 2, kt & 1);
        CPASYNC_COMMIT();
    }

    // ---- finalize: O /= l, write fp16 [hi|lo] rows of g_as ----
    float inv0 = 1.0f / l0, inv1 = 1.0f / l1;
    int r0 = qw + g, r1 = qw + g + 8;
    __half* ab = outs + (size_t)(b * TSEQ) * K2 + h * 64;
    uint32_t* p0 = (uint32_t*)(ab + (size_t)r0 * K2);
    uint32_t* p1 = (uint32_t*)(ab + (size_t)r1 * K2);
    #pragma unroll
    for (int nt = 0; nt < 8; nt++) {
        int c2 = (nt * 8 + 2 * t) >> 1;      // uint32 index within row
        float y00 = o[nt][0] * inv0, y01 = o[nt][1] * inv0;
        float y10 = o[nt][2] * inv1, y11 = o[nt][3] * inv1;
        uint32_t h0p, h1p;
        PACK_F16X2(h0p, y00, y01);
        PACK_F16X2(h1p, y10, y11);
        __half2 hh0 = *reinterpret_cast<__half2*>(&h0p);
        __half2 hh1 = *reinterpret_cast<__half2*>(&h1p);
        uint32_t l0p, l1p;
        PACK_F16X2(l0p, y00 - __low2float(hh0), y01 - __high2float(hh0));
        PACK_F16X2(l1p, y10 - __low2float(hh1), y11 - __high2float(hh1));
        p0[c2] = h0p; p0[c2 + 512] = l0p;
        p1[c2] = h1p; p1[c2 + 512] = l1p;
    }
}

// ---------------------------------------------------------------------------
// Launch
// ---------------------------------------------------------------------------
extern "C" void kernel_launch(void* const* d_in, const int* in_sizes, int n_in,
                              void* d_out, int out_size)
{
    const float* x      = (const float*)d_in[0];
    const float* W_qkv  = (const float*)d_in[1];
    const float* b_qkv  = (const float*)d_in[2];
    const float* W_proj = (const float*)d_in[3];
    const float* b_proj = (const float*)d_in[4];
    float* out = (float*)d_out;

    __half *xs, *as, *wqs, *wps;
    char *qsp, *ksp, *vsp;
    cudaGetSymbolAddress((void**)&xs,  g_xs);
    cudaGetSymbolAddress((void**)&as,  g_as);
    cudaGetSymbolAddress((void**)&wqs, g_wqs);
    cudaGetSymbolAddress((void**)&wps, g_wps);
    cudaGetSymbolAddress((void**)&qsp, g_qs);
    cudaGetSymbolAddress((void**)&ksp, g_ksp);
    cudaGetSymbolAddress((void**)&vsp, g_vsp);

    cudaFuncSetAttribute(gemm_f16_kernel,
                         cudaFuncAttributeMaxDynamicSharedMemorySize, GEMM_SMEM);
    cudaFuncSetAttribute(flash_hmma_kernel,
                         cudaFuncAttributeMaxDynamicSharedMemorySize, FLASH_SMEM);

    // fp16 2-product splits: A operands [hi|lo], B operands [hi|hi]
    split16_kernel<<<BT * CDIM / 8 / 256, 256>>>(x, xs, 0);
    split16_kernel<<<3 * CDIM * CDIM / 8 / 256, 256>>>(W_qkv, wqs, 1);
    split16_kernel<<<CDIM * CDIM / 8 / 256, 256>>>(W_proj, wps, 1);

    // 1) QKV projection (fp16 2-product); epilogue writes fp16 Q/K/V blocks
    gemm_f16_kernel<<<dim3(3 * CDIM / 128, BT / 128), 256, GEMM_SMEM>>>(
        xs, wqs, b_qkv, nullptr, BT, 3 * CDIM, K2, qsp, ksp, vsp, 1);

    // 2) Causal flash attention (fp16 2-combo HMMA); fp16 [hi|lo] output
    flash_hmma_kernel<<<dim3(TSEQ / 128, NH, BATCH), 256, FLASH_SMEM>>>(
        qsp, ksp, vsp, as);

    // 3) Output projection (fp16 2-product, fp32 + bias into d_out)
    gemm_f16_kernel<<<dim3(CDIM / 128, BT / 128), 256, GEMM_SMEM>>>(
        as, wps, b_proj, out, BT, CDIM, K2, nullptr, nullptr, nullptr, 0);
}